// round 13
// baseline (speedup 1.0000x reference)
#include <cuda_runtime.h>
#include <math.h>

#define N_NODES 50000
#define N_EDGES 500000
#define NF      128
#define NH      4
#define NEG_SLOPE 0.2f
#define BN_EPS 1e-5f
#define SCAN_B  1024
#define N_SCANB ((N_NODES + SCAN_B - 1) / SCAN_B)   // 49

// ---------------- scratch (device globals; no allocation allowed) ----------
__device__ float g_h  [N_NODES * NF];
__device__ float g_h1 [N_NODES * NF];
__device__ float g_fsa[N_NODES * NF];
__device__ float g_fsb[N_NODES * NF];
__device__ float g_h2 [N_NODES * NF];
__device__ float g_ela[N_NODES * NH];
__device__ float g_era[N_NODES * NH];
__device__ float g_elb[N_NODES * NH];
__device__ float g_erb[N_NODES * NH];
__device__ double g_sum[3][NF];
__device__ double g_sq [3][NF];
// CSR (2 relations)
__device__ int g_deg   [2][N_NODES];
__device__ int g_rowptr[2][N_NODES + 1];
__device__ int g_cursor[2][N_NODES];
__device__ int g_colsrc[2][N_EDGES];
__device__ int g_bsum  [2][N_SCANB];

// ---------------- CSR build (both relations in one grid) ----------------
__global__ void zero_deg_all() {      // also zeroes ALL BN stats (global index)
    int i = blockIdx.x * blockDim.x + threadIdx.x;
    if (i < 2 * N_NODES) ((int*)g_deg)[i] = 0;
    if (i < 3 * NF) {
        ((double*)g_sum)[i] = 0.0;
        ((double*)g_sq)[i]  = 0.0;
    }
}

__global__ void hist_deg_all(const int* __restrict__ dst) {   // dst = [2][E]
    int i = blockIdx.x * blockDim.x + threadIdx.x;
    if (i >= 2 * N_EDGES) return;
    int r = i / N_EDGES;
    atomicAdd(&g_deg[r][dst[i]], 1);
}

__global__ __launch_bounds__(SCAN_B)
void scan_blocks_all() {
    __shared__ int tmp[SCAN_B];
    int r  = blockIdx.x / N_SCANB;
    int bb = blockIdx.x % N_SCANB;
    int i = bb * SCAN_B + threadIdx.x;
    int v = (i < N_NODES) ? g_deg[r][i] : 0;
    tmp[threadIdx.x] = v;
    __syncthreads();
    for (int off = 1; off < SCAN_B; off <<= 1) {
        int t = (threadIdx.x >= off) ? tmp[threadIdx.x - off] : 0;
        __syncthreads();
        tmp[threadIdx.x] += t;
        __syncthreads();
    }
    if (i < N_NODES) g_rowptr[r][i] = tmp[threadIdx.x] - v;   // exclusive
    if (threadIdx.x == SCAN_B - 1) g_bsum[r][bb] = tmp[SCAN_B - 1];
}

__global__ void scan_bsum_all() {     // 2 blocks, one per relation
    __shared__ int s[64];
    int r = blockIdx.x;
    int v = (threadIdx.x < N_SCANB) ? g_bsum[r][threadIdx.x] : 0;
    s[threadIdx.x] = v;
    __syncthreads();
    for (int off = 1; off < 64; off <<= 1) {
        int t = (threadIdx.x >= off) ? s[threadIdx.x - off] : 0;
        __syncthreads();
        s[threadIdx.x] += t;
        __syncthreads();
    }
    if (threadIdx.x < N_SCANB) g_bsum[r][threadIdx.x] = s[threadIdx.x] - v;  // exclusive
}

__global__ void scan_finish_all() {
    int i = blockIdx.x * blockDim.x + threadIdx.x;
    if (i >= 2 * N_NODES) return;
    int r = i / N_NODES;
    int n = i % N_NODES;
    int v = g_rowptr[r][n] + g_bsum[r][n / SCAN_B];
    g_rowptr[r][n] = v;
    g_cursor[r][n] = v;
    if (n == 0) g_rowptr[r][N_NODES] = N_EDGES;
}

__global__ void scatter_csr_all(const int* __restrict__ src, const int* __restrict__ dst) {
    int i = blockIdx.x * blockDim.x + threadIdx.x;
    if (i >= 2 * N_EDGES) return;
    int r = i / N_EDGES;
    int p = atomicAdd(&g_cursor[r][dst[i]], 1);
    g_colsrc[r][p] = src[i];
}

// ---------------- software-pipelined SGEMM core ----------------
__device__ __forceinline__ void cp_async16(void* smem, const void* gmem) {
    unsigned sa = (unsigned)__cvta_generic_to_shared(smem);
    asm volatile("cp.async.cg.shared.global [%0], [%1], 16;\n"
                 :: "r"(sa), "l"(gmem));
}
__device__ __forceinline__ void cp_commit() {
    asm volatile("cp.async.commit_group;\n");
}
__device__ __forceinline__ void cp_wait0() {
    asm volatile("cp.async.wait_group 0;\n" ::: "memory");
}

// shared device body: one 128-row tile of C = A@W (+bias) (+attn epilogue)
// (+ optional fused BN stats via psum/psq smem and slot)
__device__ __forceinline__ void gemm_body(
    const float* __restrict__ A, const float* __restrict__ W,
    const float* __restrict__ bias, float* __restrict__ C,
    const float* __restrict__ al, const float* __restrict__ ar,
    float* __restrict__ elo, float* __restrict__ ero,
    float As[2][8][128], float Ws[2][8][128],
    float (*psum)[NF], float (*psq)[NF], int slot) {

    const int tid = threadIdx.x;
    const int tx = tid & 15;
    const int ty = tid >> 4;
    const int rb = blockIdx.x * 128;

    const int arow = tid >> 1;
    const int acol = (tid & 1) * 4;
    const int wrow = tid >> 5;
    const int wcol = (tid & 31) * 4;
    const int gr = rb + arow;
    const bool arow_ok = (gr < N_NODES);

    float acc[8][8];
#pragma unroll
    for (int i = 0; i < 8; i++)
#pragma unroll
        for (int j = 0; j < 8; j++) acc[i][j] = 0.f;

    float4 av = make_float4(0.f, 0.f, 0.f, 0.f);
    if (arow_ok) av = *(const float4*)&A[(size_t)gr * NF + acol];
    cp_async16(&Ws[0][wrow][wcol], &W[(size_t)wrow * NF + wcol]);
    cp_commit();
    As[0][acol + 0][arow] = av.x;
    As[0][acol + 1][arow] = av.y;
    As[0][acol + 2][arow] = av.z;
    As[0][acol + 3][arow] = av.w;
    cp_wait0();
    __syncthreads();

    int buf = 0;
    for (int t = 0; t < 16; t++) {
        const int kc = t * 8;
        const bool has_next = (t + 1 < 16);
        float4 avn;
        if (has_next) {
            avn = make_float4(0.f, 0.f, 0.f, 0.f);
            if (arow_ok) avn = *(const float4*)&A[(size_t)gr * NF + kc + 8 + acol];
            cp_async16(&Ws[buf ^ 1][wrow][wcol], &W[(size_t)(kc + 8 + wrow) * NF + wcol]);
            cp_commit();
        }

#pragma unroll
        for (int kk = 0; kk < 8; kk++) {
            float a[8], b[8];
            *(float4*)&a[0] = *(float4*)&As[buf][kk][ty * 8];
            *(float4*)&a[4] = *(float4*)&As[buf][kk][ty * 8 + 4];
            *(float4*)&b[0] = *(float4*)&Ws[buf][kk][tx * 8];
            *(float4*)&b[4] = *(float4*)&Ws[buf][kk][tx * 8 + 4];
#pragma unroll
            for (int i = 0; i < 8; i++)
#pragma unroll
                for (int j = 0; j < 8; j++)
                    acc[i][j] = fmaf(a[i], b[j], acc[i][j]);
        }

        if (has_next) {
            As[buf ^ 1][acol + 0][arow] = avn.x;
            As[buf ^ 1][acol + 1][arow] = avn.y;
            As[buf ^ 1][acol + 2][arow] = avn.z;
            As[buf ^ 1][acol + 3][arow] = avn.w;
            cp_wait0();
        }
        __syncthreads();
        buf ^= 1;
    }

    const int cb = tx * 8;
    float bcol[8];
#pragma unroll
    for (int j = 0; j < 8; j++) bcol[j] = bias ? bias[cb + j] : 0.f;
    float alv[8], arv[8];
    if (elo) {
#pragma unroll
        for (int j = 0; j < 8; j++) { alv[j] = al[cb + j]; arv[j] = ar[cb + j]; }
    }
    const int hh = tx >> 2;

    float ps[8], pq[8];
    if (psum) {
#pragma unroll
        for (int j = 0; j < 8; j++) { ps[j] = 0.f; pq[j] = 0.f; }
    }

#pragma unroll
    for (int i = 0; i < 8; i++) {
        int row = rb + ty * 8 + i;
        if (row < N_NODES) {
            float v0 = acc[i][0] + bcol[0], v1 = acc[i][1] + bcol[1];
            float v2 = acc[i][2] + bcol[2], v3 = acc[i][3] + bcol[3];
            float v4 = acc[i][4] + bcol[4], v5 = acc[i][5] + bcol[5];
            float v6 = acc[i][6] + bcol[6], v7 = acc[i][7] + bcol[7];
            *(float4*)&C[(size_t)row * NF + cb]     = make_float4(v0, v1, v2, v3);
            *(float4*)&C[(size_t)row * NF + cb + 4] = make_float4(v4, v5, v6, v7);
            if (psum) {
                ps[0] += v0; pq[0] += v0 * v0; ps[1] += v1; pq[1] += v1 * v1;
                ps[2] += v2; pq[2] += v2 * v2; ps[3] += v3; pq[3] += v3 * v3;
                ps[4] += v4; pq[4] += v4 * v4; ps[5] += v5; pq[5] += v5 * v5;
                ps[6] += v6; pq[6] += v6 * v6; ps[7] += v7; pq[7] += v7 * v7;
            }
        }
        if (elo) {
            float p = 0.f, q = 0.f;
#pragma unroll
            for (int j = 0; j < 8; j++) {
                p = fmaf(acc[i][j], alv[j], p);
                q = fmaf(acc[i][j], arv[j], q);
            }
            p += __shfl_down_sync(0xffffffffu, p, 1, 4);
            p += __shfl_down_sync(0xffffffffu, p, 2, 4);
            q += __shfl_down_sync(0xffffffffu, q, 1, 4);
            q += __shfl_down_sync(0xffffffffu, q, 2, 4);
            if ((tx & 3) == 0 && row < N_NODES) {
                elo[row * NH + hh] = p;
                ero[row * NH + hh] = q;
            }
        }
    }

    if (psum) {
#pragma unroll
        for (int j = 0; j < 8; j++) { psum[ty][cb + j] = ps[j]; psq[ty][cb + j] = pq[j]; }
        __syncthreads();
        if (tid < NF) {
            double s = 0.0, q = 0.0;
#pragma unroll
            for (int g = 0; g < 16; g++) { s += (double)psum[g][tid]; q += (double)psq[g][tid]; }
            atomicAdd(&g_sum[slot][tid], s);
            atomicAdd(&g_sq[slot][tid], q);
        }
    }
}

// classifier GEMM with fused BN stats
__global__ __launch_bounds__(256, 2)
void gemm128_stats(const float* __restrict__ A, const float* __restrict__ W,
                   const float* __restrict__ bias, float* __restrict__ C, int slot) {
    __shared__ float As[2][8][128];
    __shared__ float Ws[2][8][128];
    __shared__ float psum[16][NF];
    __shared__ float psq[16][NF];
    gemm_body(A, W, bias, C, nullptr, nullptr, nullptr, nullptr, As, Ws, psum, psq, slot);
}

// batched tri-GEMM: blockIdx.y = 0 skip, 1 fc0(+attn), 2 fc1(+attn)
__global__ __launch_bounds__(256, 2)
void gemm128x3(const float* __restrict__ A,
               const float* __restrict__ Wskip, const float* __restrict__ bskip,
               const float* __restrict__ Wfc0, const float* __restrict__ Wfc1,
               const float* __restrict__ al0, const float* __restrict__ ar0,
               const float* __restrict__ al1, const float* __restrict__ ar1,
               float* __restrict__ Cskip, float* __restrict__ Cfc0,
               float* __restrict__ Cfc1,
               float* __restrict__ el0, float* __restrict__ er0,
               float* __restrict__ el1, float* __restrict__ er1) {
    __shared__ float As[2][8][128];
    __shared__ float Ws[2][8][128];
    if (blockIdx.y == 0) {
        gemm_body(A, Wskip, bskip, Cskip, nullptr, nullptr, nullptr, nullptr, As, Ws,
                  nullptr, nullptr, 0);
    } else if (blockIdx.y == 1) {
        gemm_body(A, Wfc0, nullptr, Cfc0, al0, ar0, el0, er0, As, Ws, nullptr, nullptr, 0);
    } else {
        gemm_body(A, Wfc1, nullptr, Cfc1, al1, ar1, el1, er1, As, Ws, nullptr, nullptr, 0);
    }
}

// ---------------- fused dual-relation GAT agg: 2 warps per node ------------
// index-prefetched edge loop: next quad of colsrc issued before current gathers
__device__ __forceinline__ float agg_one_rel(
    int r, int d, int h, int co,
    const float* __restrict__ el, const float* __restrict__ er,
    const float* __restrict__ fs, float4* acc_out) {
    const int beg = g_rowptr[r][d];
    const int end = g_rowptr[r][d + 1];
    const float er_h = er[d * NH + h];
    float4 acc = make_float4(0.f, 0.f, 0.f, 0.f);
    float sh = 0.f;
    const int n4 = (end - beg) >> 2;
    int s0 = 0, s1 = 0, s2 = 0, s3 = 0;
    if (n4 > 0) {
        s0 = g_colsrc[r][beg];     s1 = g_colsrc[r][beg + 1];
        s2 = g_colsrc[r][beg + 2]; s3 = g_colsrc[r][beg + 3];
    }
    for (int it = 0; it < n4; it++) {
        int t0 = s0, t1 = s1, t2 = s2, t3 = s3;
        int nb = beg + (it + 1) * 4;
        if (it + 1 < n4) {                    // prefetch next quad of indices
            s0 = g_colsrc[r][nb];     s1 = g_colsrc[r][nb + 1];
            s2 = g_colsrc[r][nb + 2]; s3 = g_colsrc[r][nb + 3];
        }
        float el0 = el[t0 * NH + h];
        float el1 = el[t1 * NH + h];
        float el2 = el[t2 * NH + h];
        float el3 = el[t3 * NH + h];
        float4 f0 = *(const float4*)&fs[(size_t)t0 * NF + co];
        float4 f1 = *(const float4*)&fs[(size_t)t1 * NF + co];
        float4 f2 = *(const float4*)&fs[(size_t)t2 * NF + co];
        float4 f3 = *(const float4*)&fs[(size_t)t3 * NF + co];
        float v0 = el0 + er_h; v0 = v0 > 0.f ? v0 : NEG_SLOPE * v0;
        float v1 = el1 + er_h; v1 = v1 > 0.f ? v1 : NEG_SLOPE * v1;
        float v2 = el2 + er_h; v2 = v2 > 0.f ? v2 : NEG_SLOPE * v2;
        float v3 = el3 + er_h; v3 = v3 > 0.f ? v3 : NEG_SLOPE * v3;
        float w0 = expf(v0), w1 = expf(v1), w2 = expf(v2), w3 = expf(v3);
        sh += (w0 + w1) + (w2 + w3);
        acc.x = fmaf(w0, f0.x, acc.x); acc.y = fmaf(w0, f0.y, acc.y);
        acc.z = fmaf(w0, f0.z, acc.z); acc.w = fmaf(w0, f0.w, acc.w);
        acc.x = fmaf(w1, f1.x, acc.x); acc.y = fmaf(w1, f1.y, acc.y);
        acc.z = fmaf(w1, f1.z, acc.z); acc.w = fmaf(w1, f1.w, acc.w);
        acc.x = fmaf(w2, f2.x, acc.x); acc.y = fmaf(w2, f2.y, acc.y);
        acc.z = fmaf(w2, f2.z, acc.z); acc.w = fmaf(w2, f2.w, acc.w);
        acc.x = fmaf(w3, f3.x, acc.x); acc.y = fmaf(w3, f3.y, acc.y);
        acc.z = fmaf(w3, f3.z, acc.z); acc.w = fmaf(w3, f3.w, acc.w);
    }
    for (int e = beg + n4 * 4; e < end; e++) {
        int s = g_colsrc[r][e];
        float elA = el[s * NH + h];
        float4 fa = *(const float4*)&fs[(size_t)s * NF + co];
        float vA = elA + er_h; vA = vA > 0.f ? vA : NEG_SLOPE * vA;
        float wA = expf(vA);
        sh += wA;
        acc.x = fmaf(wA, fa.x, acc.x); acc.y = fmaf(wA, fa.y, acc.y);
        acc.z = fmaf(wA, fa.z, acc.z); acc.w = fmaf(wA, fa.w, acc.w);
    }
    *acc_out = acc;
    return (end > beg) ? (1.f / sh) : 0.f;
}

// block = 256 thr = 8 warps = 4 nodes x 2 relations; grid = 12500
__global__ __launch_bounds__(256)
void gat_agg2(const float* __restrict__ ela, const float* __restrict__ era,
              const float* __restrict__ fsa,
              const float* __restrict__ elb, const float* __restrict__ erb,
              const float* __restrict__ fsb,
              const float* __restrict__ h1,
              const float* __restrict__ cb0, const float* __restrict__ cb1,
              float* __restrict__ t_out, int slot) {
    __shared__ float ts[8][NF];
    const int wid = threadIdx.x >> 5;
    const int lane = threadIdx.x & 31;
    const int rel = wid & 1;
    const int d = blockIdx.x * 4 + (wid >> 1);
    const int h = lane >> 3;
    const int co = lane * 4;

    const float* el = rel ? elb : ela;
    const float* er = rel ? erb : era;
    const float* fs = rel ? fsb : fsa;

    float4 acc;
    float inv = agg_one_rel(rel, d, h, co, el, er, fs, &acc);
    // normalized per-relation partial
    *(float4*)&ts[wid][co] = make_float4(acc.x * inv, acc.y * inv,
                                         acc.z * inv, acc.w * inv);
    __syncthreads();

    if (wid < 4) {                              // combine + finalize node d2
        const int d2 = blockIdx.x * 4 + wid;
        float4 pa = *(float4*)&ts[2 * wid][co];
        float4 pb = *(float4*)&ts[2 * wid + 1][co];
        float4 b0 = *(const float4*)&cb0[co];
        float4 b1 = *(const float4*)&cb1[co];
        float4 hv = *(const float4*)&h1[(size_t)d2 * NF + co];
        float4 v;
        v.x = pa.x + pb.x + b0.x + b1.x;
        v.y = pa.y + pb.y + b0.y + b1.y;
        v.z = pa.z + pb.z + b0.z + b1.z;
        v.w = pa.w + pb.w + b0.w + b1.w;
        v.x = (v.x > 0.f ? v.x : 0.f) + hv.x;
        v.y = (v.y > 0.f ? v.y : 0.f) + hv.y;
        v.z = (v.z > 0.f ? v.z : 0.f) + hv.z;
        v.w = (v.w > 0.f ? v.w : 0.f) + hv.w;
        *(float4*)&t_out[(size_t)d2 * NF + co] = v;
        *(float4*)&ts[2 * wid][co] = v;          // stage combined for stats
    }
    __syncthreads();

    if (threadIdx.x < NF) {                     // BN stats over 4 combined rows
        int c = threadIdx.x;
        double s = 0.0, q = 0.0;
#pragma unroll
        for (int w = 0; w < 4; w++) {
            float x = ts[2 * w][c];
            s += x;
            q += (double)x * x;
        }
        atomicAdd(&g_sum[slot][c], s);
        atomicAdd(&g_sq[slot][c], q);
    }
}

// ---------------- normalize ----------------
#define RPB 64
__global__ void normalize128(const float* __restrict__ x, const float* __restrict__ g,
                             const float* __restrict__ b, float* __restrict__ y,
                             int do_relu, int slot) {
    int col = threadIdx.x;
    double mu = g_sum[slot][col] / (double)N_NODES;
    double var = g_sq[slot][col] / (double)N_NODES - mu * mu;
    float sc = g[col] * rsqrtf((float)var + BN_EPS);
    float sh = b[col] - (float)mu * sc;
    int r0 = blockIdx.x * RPB;
    for (int r = 0; r < RPB; r++) {
        int row = r0 + r;
        if (row >= N_NODES) break;
        float v = x[(size_t)row * NF + col] * sc + sh;
        if (do_relu) v = v > 0.f ? v : 0.f;
        y[(size_t)row * NF + col] = v;
    }
}

// ---------------- final 128 -> 16 GEMM, BN affine+relu fused in load -------
__global__ __launch_bounds__(128)
void gemm_out(const float* __restrict__ x, const float* __restrict__ clf_g,
              const float* __restrict__ clf_b, const float* __restrict__ W2,
              const float* __restrict__ b2, float* __restrict__ out, int slot) {
    __shared__ float xs[8][NF];
    int tid = threadIdx.x;
    int r0 = blockIdx.x * 8;
    double mu = g_sum[slot][tid] / (double)N_NODES;
    double var = g_sq[slot][tid] / (double)N_NODES - mu * mu;
    float sc = clf_g[tid] * rsqrtf((float)var + BN_EPS);
    float sh = clf_b[tid] - (float)mu * sc;
#pragma unroll
    for (int i = 0; i < 8; i++) {
        int row = r0 + i;
        float v = (row < N_NODES) ? fmaf(x[(size_t)row * NF + tid], sc, sh) : 0.f;
        xs[i][tid] = v > 0.f ? v : 0.f;
    }
    __syncthreads();
    int row = tid >> 4;
    int c = tid & 15;
    float acc = b2[c];
#pragma unroll 8
    for (int k = 0; k < NF; k++) acc = fmaf(xs[row][k], W2[k * 16 + c], acc);
    if (r0 + row < N_NODES) out[(size_t)(r0 + row) * 16 + c] = acc;
}

// ---------------- host ----------------
extern "C" void kernel_launch(void* const* d_in, const int* in_sizes, int n_in,
                              void* d_out, int out_size) {
    const float* feat     = (const float*)d_in[0];
    const float* fc_W     = (const float*)d_in[1];
    const float* attn_l   = (const float*)d_in[2];
    const float* attn_r   = (const float*)d_in[3];
    const float* conv_b   = (const float*)d_in[4];
    const float* skip_W   = (const float*)d_in[5];
    const float* skip_b   = (const float*)d_in[6];
    const float* norm_g   = (const float*)d_in[7];
    const float* norm_b   = (const float*)d_in[8];
    const float* clf_W1   = (const float*)d_in[9];
    const float* clf_b1   = (const float*)d_in[10];
    const float* clf_g    = (const float*)d_in[11];
    const float* clf_b    = (const float*)d_in[12];
    const float* clf_W2   = (const float*)d_in[13];
    const float* clf_b2   = (const float*)d_in[14];
    const int*   src      = (const int*)d_in[15];
    const int*   dst      = (const int*)d_in[16];
    float* out = (float*)d_out;

    float *h, *h1, *fsa, *fsb, *h2, *ela, *era, *elb, *erb;
    cudaGetSymbolAddress((void**)&h,   g_h);
    cudaGetSymbolAddress((void**)&h1,  g_h1);
    cudaGetSymbolAddress((void**)&fsa, g_fsa);
    cudaGetSymbolAddress((void**)&fsb, g_fsb);
    cudaGetSymbolAddress((void**)&h2,  g_h2);
    cudaGetSymbolAddress((void**)&ela, g_ela);
    cudaGetSymbolAddress((void**)&era, g_era);
    cudaGetSymbolAddress((void**)&elb, g_elb);
    cudaGetSymbolAddress((void**)&erb, g_erb);

    const int gemm_grid  = (N_NODES + 127) / 128;        // 391
    const int node2_grid = (2 * N_NODES + 255) / 256;
    const int edge2_grid = (2 * N_EDGES + 255) / 256;
    const int agg_grid   = (N_NODES + 3) / 4;            // 12500
    const int bn_grid    = (N_NODES + RPB - 1) / RPB;    // 782

    // lazily-created side stream + events for the CSR fork (host resources only)
    static cudaStream_t s_csr = nullptr;
    static cudaEvent_t ev_fork = nullptr, ev_join = nullptr;
    if (s_csr == nullptr) {
        cudaStreamCreate(&s_csr);
        cudaEventCreateWithFlags(&ev_fork, cudaEventDisableTiming);
        cudaEventCreateWithFlags(&ev_join, cudaEventDisableTiming);
    }

    // ---- fork: CSR build + stats zero on side stream ----
    cudaEventRecord(ev_fork, 0);
    cudaStreamWaitEvent(s_csr, ev_fork, 0);
    zero_deg_all<<<node2_grid, 256, 0, s_csr>>>();
    hist_deg_all<<<edge2_grid, 256, 0, s_csr>>>(dst);
    scan_blocks_all<<<2 * N_SCANB, SCAN_B, 0, s_csr>>>();
    scan_bsum_all<<<2, 64, 0, s_csr>>>();
    scan_finish_all<<<node2_grid, 256, 0, s_csr>>>();
    scatter_csr_all<<<edge2_grid, 256, 0, s_csr>>>(src, dst);
    cudaEventRecord(ev_join, s_csr);

    // ---- main stream: layer-1 GEMMs run concurrently with the CSR build ----
    {
        dim3 g3(gemm_grid, 3);
        gemm128x3<<<g3, 256>>>(feat,
                               skip_W, skip_b,
                               fc_W, fc_W + (size_t)NF * NF,
                               attn_l, attn_r,
                               attn_l + NF, attn_r + NF,
                               h1, fsa, fsb, ela, era, elb, erb);
    }
    cudaStreamWaitEvent(0, ev_join, 0);   // join before first CSR consumer

    for (int l = 0; l < 2; l++) {
        int lr0 = l * 2, lr1 = l * 2 + 1;
        if (l > 0) {
            dim3 g3(gemm_grid, 3);
            gemm128x3<<<g3, 256>>>(h,
                                   skip_W + l * NF * NF, skip_b + l * NF,
                                   fc_W + (size_t)lr0 * NF * NF,
                                   fc_W + (size_t)lr1 * NF * NF,
                                   attn_l + lr0 * NF, attn_r + lr0 * NF,
                                   attn_l + lr1 * NF, attn_r + lr1 * NF,
                                   h1, fsa, fsb, ela, era, elb, erb);
        }
        gat_agg2<<<agg_grid, 256>>>(ela, era, fsa, elb, erb, fsb,
                                    h1, conv_b + lr0 * NF, conv_b + lr1 * NF,
                                    h2, l);
        normalize128<<<bn_grid, 128>>>(h2, norm_g + l * NF, norm_b + l * NF, h, 0, l);
    }

    // classifier: GEMM with fused BN stats, then BN+relu fused into gemm_out
    gemm128_stats<<<gemm_grid, 256>>>(h, clf_W1, clf_b1, h1, 2);
    gemm_out<<<(N_NODES + 7) / 8, 128>>>(h1, clf_g, clf_b, clf_W2, clf_b2, out, 2);
}

// round 14
// speedup vs baseline: 1.1044x; 1.1044x over previous
#include <cuda_runtime.h>
#include <math.h>

#define N_NODES 50000
#define N_EDGES 500000
#define NF      128
#define NH      4
#define NEG_SLOPE 0.2f
#define BN_EPS 1e-5f
#define SCAN_B  1024
#define N_SCANB ((N_NODES + SCAN_B - 1) / SCAN_B)   // 49

// ---------------- scratch (device globals; no allocation allowed) ----------
__device__ float g_h  [N_NODES * NF];
__device__ float g_h1 [N_NODES * NF];
__device__ float g_fsa[N_NODES * NF];
__device__ float g_fsb[N_NODES * NF];
__device__ float g_h2 [N_NODES * NF];
__device__ float g_ela[N_NODES * NH];
__device__ float g_era[N_NODES * NH];
__device__ float g_elb[N_NODES * NH];
__device__ float g_erb[N_NODES * NH];
__device__ double g_sum[3][NF];
__device__ double g_sq [3][NF];
// CSR (2 relations)
__device__ int g_deg   [2][N_NODES];
__device__ int g_rowptr[2][N_NODES + 1];
__device__ int g_cursor[2][N_NODES];
__device__ int g_colsrc[2][N_EDGES];
__device__ int g_bsum  [2][N_SCANB];

// ---------------- CSR build (both relations in one grid) ----------------
__global__ void zero_deg_all() {      // also zeroes ALL BN stats (global index)
    int i = blockIdx.x * blockDim.x + threadIdx.x;
    if (i < 2 * N_NODES) ((int*)g_deg)[i] = 0;
    if (i < 3 * NF) {
        ((double*)g_sum)[i] = 0.0;
        ((double*)g_sq)[i]  = 0.0;
    }
}

__global__ void hist_deg_all(const int* __restrict__ dst) {   // dst = [2][E]
    int i = blockIdx.x * blockDim.x + threadIdx.x;
    if (i >= 2 * N_EDGES) return;
    int r = i / N_EDGES;
    atomicAdd(&g_deg[r][dst[i]], 1);
}

__global__ __launch_bounds__(SCAN_B)
void scan_blocks_all() {
    __shared__ int tmp[SCAN_B];
    int r  = blockIdx.x / N_SCANB;
    int bb = blockIdx.x % N_SCANB;
    int i = bb * SCAN_B + threadIdx.x;
    int v = (i < N_NODES) ? g_deg[r][i] : 0;
    tmp[threadIdx.x] = v;
    __syncthreads();
    for (int off = 1; off < SCAN_B; off <<= 1) {
        int t = (threadIdx.x >= off) ? tmp[threadIdx.x - off] : 0;
        __syncthreads();
        tmp[threadIdx.x] += t;
        __syncthreads();
    }
    if (i < N_NODES) g_rowptr[r][i] = tmp[threadIdx.x] - v;   // exclusive
    if (threadIdx.x == SCAN_B - 1) g_bsum[r][bb] = tmp[SCAN_B - 1];
}

__global__ void scan_bsum_all() {     // 2 blocks, one per relation
    __shared__ int s[64];
    int r = blockIdx.x;
    int v = (threadIdx.x < N_SCANB) ? g_bsum[r][threadIdx.x] : 0;
    s[threadIdx.x] = v;
    __syncthreads();
    for (int off = 1; off < 64; off <<= 1) {
        int t = (threadIdx.x >= off) ? s[threadIdx.x - off] : 0;
        __syncthreads();
        s[threadIdx.x] += t;
        __syncthreads();
    }
    if (threadIdx.x < N_SCANB) g_bsum[r][threadIdx.x] = s[threadIdx.x] - v;  // exclusive
}

__global__ void scan_finish_all() {
    int i = blockIdx.x * blockDim.x + threadIdx.x;
    if (i >= 2 * N_NODES) return;
    int r = i / N_NODES;
    int n = i % N_NODES;
    int v = g_rowptr[r][n] + g_bsum[r][n / SCAN_B];
    g_rowptr[r][n] = v;
    g_cursor[r][n] = v;
    if (n == 0) g_rowptr[r][N_NODES] = N_EDGES;
}

__global__ void scatter_csr_all(const int* __restrict__ src, const int* __restrict__ dst) {
    int i = blockIdx.x * blockDim.x + threadIdx.x;
    if (i >= 2 * N_EDGES) return;
    int r = i / N_EDGES;
    int p = atomicAdd(&g_cursor[r][dst[i]], 1);
    g_colsrc[r][p] = src[i];
}

// ---------------- software-pipelined SGEMM core ----------------
__device__ __forceinline__ void cp_async16(void* smem, const void* gmem) {
    unsigned sa = (unsigned)__cvta_generic_to_shared(smem);
    asm volatile("cp.async.cg.shared.global [%0], [%1], 16;\n"
                 :: "r"(sa), "l"(gmem));
}
__device__ __forceinline__ void cp_commit() {
    asm volatile("cp.async.commit_group;\n");
}
__device__ __forceinline__ void cp_wait0() {
    asm volatile("cp.async.wait_group 0;\n" ::: "memory");
}

// shared device body: one 128-row tile of C = A@W (+bias) (+attn epilogue)
// (+ optional fused BN stats via psum/psq smem and slot)
__device__ __forceinline__ void gemm_body(
    const float* __restrict__ A, const float* __restrict__ W,
    const float* __restrict__ bias, float* __restrict__ C,
    const float* __restrict__ al, const float* __restrict__ ar,
    float* __restrict__ elo, float* __restrict__ ero,
    float As[2][8][128], float Ws[2][8][128],
    float (*psum)[NF], float (*psq)[NF], int slot) {

    const int tid = threadIdx.x;
    const int tx = tid & 15;
    const int ty = tid >> 4;
    const int rb = blockIdx.x * 128;

    const int arow = tid >> 1;
    const int acol = (tid & 1) * 4;
    const int wrow = tid >> 5;
    const int wcol = (tid & 31) * 4;
    const int gr = rb + arow;
    const bool arow_ok = (gr < N_NODES);

    float acc[8][8];
#pragma unroll
    for (int i = 0; i < 8; i++)
#pragma unroll
        for (int j = 0; j < 8; j++) acc[i][j] = 0.f;

    float4 av = make_float4(0.f, 0.f, 0.f, 0.f);
    if (arow_ok) av = *(const float4*)&A[(size_t)gr * NF + acol];
    cp_async16(&Ws[0][wrow][wcol], &W[(size_t)wrow * NF + wcol]);
    cp_commit();
    As[0][acol + 0][arow] = av.x;
    As[0][acol + 1][arow] = av.y;
    As[0][acol + 2][arow] = av.z;
    As[0][acol + 3][arow] = av.w;
    cp_wait0();
    __syncthreads();

    int buf = 0;
    for (int t = 0; t < 16; t++) {
        const int kc = t * 8;
        const bool has_next = (t + 1 < 16);
        float4 avn;
        if (has_next) {
            avn = make_float4(0.f, 0.f, 0.f, 0.f);
            if (arow_ok) avn = *(const float4*)&A[(size_t)gr * NF + kc + 8 + acol];
            cp_async16(&Ws[buf ^ 1][wrow][wcol], &W[(size_t)(kc + 8 + wrow) * NF + wcol]);
            cp_commit();
        }

#pragma unroll
        for (int kk = 0; kk < 8; kk++) {
            float a[8], b[8];
            *(float4*)&a[0] = *(float4*)&As[buf][kk][ty * 8];
            *(float4*)&a[4] = *(float4*)&As[buf][kk][ty * 8 + 4];
            *(float4*)&b[0] = *(float4*)&Ws[buf][kk][tx * 8];
            *(float4*)&b[4] = *(float4*)&Ws[buf][kk][tx * 8 + 4];
#pragma unroll
            for (int i = 0; i < 8; i++)
#pragma unroll
                for (int j = 0; j < 8; j++)
                    acc[i][j] = fmaf(a[i], b[j], acc[i][j]);
        }

        if (has_next) {
            As[buf ^ 1][acol + 0][arow] = avn.x;
            As[buf ^ 1][acol + 1][arow] = avn.y;
            As[buf ^ 1][acol + 2][arow] = avn.z;
            As[buf ^ 1][acol + 3][arow] = avn.w;
            cp_wait0();
        }
        __syncthreads();
        buf ^= 1;
    }

    const int cb = tx * 8;
    float bcol[8];
#pragma unroll
    for (int j = 0; j < 8; j++) bcol[j] = bias ? bias[cb + j] : 0.f;
    float alv[8], arv[8];
    if (elo) {
#pragma unroll
        for (int j = 0; j < 8; j++) { alv[j] = al[cb + j]; arv[j] = ar[cb + j]; }
    }
    const int hh = tx >> 2;

    float ps[8], pq[8];
    if (psum) {
#pragma unroll
        for (int j = 0; j < 8; j++) { ps[j] = 0.f; pq[j] = 0.f; }
    }

#pragma unroll
    for (int i = 0; i < 8; i++) {
        int row = rb + ty * 8 + i;
        if (row < N_NODES) {
            float v0 = acc[i][0] + bcol[0], v1 = acc[i][1] + bcol[1];
            float v2 = acc[i][2] + bcol[2], v3 = acc[i][3] + bcol[3];
            float v4 = acc[i][4] + bcol[4], v5 = acc[i][5] + bcol[5];
            float v6 = acc[i][6] + bcol[6], v7 = acc[i][7] + bcol[7];
            *(float4*)&C[(size_t)row * NF + cb]     = make_float4(v0, v1, v2, v3);
            *(float4*)&C[(size_t)row * NF + cb + 4] = make_float4(v4, v5, v6, v7);
            if (psum) {
                ps[0] += v0; pq[0] += v0 * v0; ps[1] += v1; pq[1] += v1 * v1;
                ps[2] += v2; pq[2] += v2 * v2; ps[3] += v3; pq[3] += v3 * v3;
                ps[4] += v4; pq[4] += v4 * v4; ps[5] += v5; pq[5] += v5 * v5;
                ps[6] += v6; pq[6] += v6 * v6; ps[7] += v7; pq[7] += v7 * v7;
            }
        }
        if (elo) {
            float p = 0.f, q = 0.f;
#pragma unroll
            for (int j = 0; j < 8; j++) {
                p = fmaf(acc[i][j], alv[j], p);
                q = fmaf(acc[i][j], arv[j], q);
            }
            p += __shfl_down_sync(0xffffffffu, p, 1, 4);
            p += __shfl_down_sync(0xffffffffu, p, 2, 4);
            q += __shfl_down_sync(0xffffffffu, q, 1, 4);
            q += __shfl_down_sync(0xffffffffu, q, 2, 4);
            if ((tx & 3) == 0 && row < N_NODES) {
                elo[row * NH + hh] = p;
                ero[row * NH + hh] = q;
            }
        }
    }

    if (psum) {
#pragma unroll
        for (int j = 0; j < 8; j++) { psum[ty][cb + j] = ps[j]; psq[ty][cb + j] = pq[j]; }
        __syncthreads();
        if (tid < NF) {
            double s = 0.0, q = 0.0;
#pragma unroll
            for (int g = 0; g < 16; g++) { s += (double)psum[g][tid]; q += (double)psq[g][tid]; }
            atomicAdd(&g_sum[slot][tid], s);
            atomicAdd(&g_sq[slot][tid], q);
        }
    }
}

// classifier GEMM with fused BN stats
__global__ __launch_bounds__(256, 2)
void gemm128_stats(const float* __restrict__ A, const float* __restrict__ W,
                   const float* __restrict__ bias, float* __restrict__ C, int slot) {
    __shared__ float As[2][8][128];
    __shared__ float Ws[2][8][128];
    __shared__ float psum[16][NF];
    __shared__ float psq[16][NF];
    gemm_body(A, W, bias, C, nullptr, nullptr, nullptr, nullptr, As, Ws, psum, psq, slot);
}

// batched tri-GEMM: blockIdx.y = 0 skip, 1 fc0(+attn), 2 fc1(+attn)
__global__ __launch_bounds__(256, 2)
void gemm128x3(const float* __restrict__ A,
               const float* __restrict__ Wskip, const float* __restrict__ bskip,
               const float* __restrict__ Wfc0, const float* __restrict__ Wfc1,
               const float* __restrict__ al0, const float* __restrict__ ar0,
               const float* __restrict__ al1, const float* __restrict__ ar1,
               float* __restrict__ Cskip, float* __restrict__ Cfc0,
               float* __restrict__ Cfc1,
               float* __restrict__ el0, float* __restrict__ er0,
               float* __restrict__ el1, float* __restrict__ er1) {
    __shared__ float As[2][8][128];
    __shared__ float Ws[2][8][128];
    if (blockIdx.y == 0) {
        gemm_body(A, Wskip, bskip, Cskip, nullptr, nullptr, nullptr, nullptr, As, Ws,
                  nullptr, nullptr, 0);
    } else if (blockIdx.y == 1) {
        gemm_body(A, Wfc0, nullptr, Cfc0, al0, ar0, el0, er0, As, Ws, nullptr, nullptr, 0);
    } else {
        gemm_body(A, Wfc1, nullptr, Cfc1, al1, ar1, el1, er1, As, Ws, nullptr, nullptr, 0);
    }
}

// ---------------- fused dual-relation GAT agg (interleaved mainloops) ------
// scalar-range tail helper (x2-unrolled)
__device__ __forceinline__ void agg_range(
    int r, int beg, int end, float er_h, int h, int co,
    const float* __restrict__ el, const float* __restrict__ fs,
    float4* acc, float* sh) {
    int e = beg;
    for (; e + 2 <= end; e += 2) {
        int sA = g_colsrc[r][e];
        int sB = g_colsrc[r][e + 1];
        float eA = el[sA * NH + h];
        float eB = el[sB * NH + h];
        float4 fA = *(const float4*)&fs[(size_t)sA * NF + co];
        float4 fB = *(const float4*)&fs[(size_t)sB * NF + co];
        float vA = eA + er_h; vA = vA > 0.f ? vA : NEG_SLOPE * vA;
        float vB = eB + er_h; vB = vB > 0.f ? vB : NEG_SLOPE * vB;
        float wA = expf(vA), wB = expf(vB);
        *sh += wA + wB;
        acc->x = fmaf(wA, fA.x, acc->x); acc->y = fmaf(wA, fA.y, acc->y);
        acc->z = fmaf(wA, fA.z, acc->z); acc->w = fmaf(wA, fA.w, acc->w);
        acc->x = fmaf(wB, fB.x, acc->x); acc->y = fmaf(wB, fB.y, acc->y);
        acc->z = fmaf(wB, fB.z, acc->z); acc->w = fmaf(wB, fB.w, acc->w);
    }
    if (e < end) {
        int s = g_colsrc[r][e];
        float eA = el[s * NH + h];
        float4 fA = *(const float4*)&fs[(size_t)s * NF + co];
        float vA = eA + er_h; vA = vA > 0.f ? vA : NEG_SLOPE * vA;
        float wA = expf(vA);
        *sh += wA;
        acc->x = fmaf(wA, fA.x, acc->x); acc->y = fmaf(wA, fA.y, acc->y);
        acc->z = fmaf(wA, fA.z, acc->z); acc->w = fmaf(wA, fA.w, acc->w);
    }
}

// warp per node (8 nodes / 256-thr block, grid 6250); both relations'
// edge quads processed per iteration -> MLP ~8 on the gather chains.
__global__ __launch_bounds__(256)
void gat_agg2(const float* __restrict__ ela, const float* __restrict__ era,
              const float* __restrict__ fsa,
              const float* __restrict__ elb, const float* __restrict__ erb,
              const float* __restrict__ fsb,
              const float* __restrict__ h1,
              const float* __restrict__ cb0, const float* __restrict__ cb1,
              float* __restrict__ t_out, int slot) {
    __shared__ float ts[8][NF];
    const int wid = threadIdx.x >> 5;
    const int lane = threadIdx.x & 31;
    const int d = blockIdx.x * 8 + wid;        // grid = 6250 -> 50000 warps
    const int h = lane >> 3;
    const int co = lane * 4;

    const int beg0 = g_rowptr[0][d], end0 = g_rowptr[0][d + 1];
    const int beg1 = g_rowptr[1][d], end1 = g_rowptr[1][d + 1];
    const int n0 = end0 - beg0, n1 = end1 - beg1;
    const float er0 = era[d * NH + h];
    const float er1 = erb[d * NH + h];

    float4 a0 = make_float4(0.f, 0.f, 0.f, 0.f);
    float4 a1 = make_float4(0.f, 0.f, 0.f, 0.f);
    float s0 = 0.f, s1 = 0.f;

    const int m = ((n0 < n1) ? n0 : n1) & ~3;   // merged quad iterations
    for (int i = 0; i < m; i += 4) {
        int p0 = beg0 + i, p1 = beg1 + i;
        int x0 = g_colsrc[0][p0],     x1 = g_colsrc[0][p0 + 1];
        int x2 = g_colsrc[0][p0 + 2], x3 = g_colsrc[0][p0 + 3];
        int y0 = g_colsrc[1][p1],     y1 = g_colsrc[1][p1 + 1];
        int y2 = g_colsrc[1][p1 + 2], y3 = g_colsrc[1][p1 + 3];
        float ex0 = ela[x0 * NH + h], ex1 = ela[x1 * NH + h];
        float ex2 = ela[x2 * NH + h], ex3 = ela[x3 * NH + h];
        float ey0 = elb[y0 * NH + h], ey1 = elb[y1 * NH + h];
        float ey2 = elb[y2 * NH + h], ey3 = elb[y3 * NH + h];
        float4 fx0 = *(const float4*)&fsa[(size_t)x0 * NF + co];
        float4 fx1 = *(const float4*)&fsa[(size_t)x1 * NF + co];
        float4 fx2 = *(const float4*)&fsa[(size_t)x2 * NF + co];
        float4 fx3 = *(const float4*)&fsa[(size_t)x3 * NF + co];
        float4 fy0 = *(const float4*)&fsb[(size_t)y0 * NF + co];
        float4 fy1 = *(const float4*)&fsb[(size_t)y1 * NF + co];
        float4 fy2 = *(const float4*)&fsb[(size_t)y2 * NF + co];
        float4 fy3 = *(const float4*)&fsb[(size_t)y3 * NF + co];
        float v;
        v = ex0 + er0; v = v > 0.f ? v : NEG_SLOPE * v; float wx0 = expf(v);
        v = ex1 + er0; v = v > 0.f ? v : NEG_SLOPE * v; float wx1 = expf(v);
        v = ex2 + er0; v = v > 0.f ? v : NEG_SLOPE * v; float wx2 = expf(v);
        v = ex3 + er0; v = v > 0.f ? v : NEG_SLOPE * v; float wx3 = expf(v);
        v = ey0 + er1; v = v > 0.f ? v : NEG_SLOPE * v; float wy0 = expf(v);
        v = ey1 + er1; v = v > 0.f ? v : NEG_SLOPE * v; float wy1 = expf(v);
        v = ey2 + er1; v = v > 0.f ? v : NEG_SLOPE * v; float wy2 = expf(v);
        v = ey3 + er1; v = v > 0.f ? v : NEG_SLOPE * v; float wy3 = expf(v);
        s0 += (wx0 + wx1) + (wx2 + wx3);
        s1 += (wy0 + wy1) + (wy2 + wy3);
        a0.x = fmaf(wx0, fx0.x, a0.x); a0.y = fmaf(wx0, fx0.y, a0.y);
        a0.z = fmaf(wx0, fx0.z, a0.z); a0.w = fmaf(wx0, fx0.w, a0.w);
        a0.x = fmaf(wx1, fx1.x, a0.x); a0.y = fmaf(wx1, fx1.y, a0.y);
        a0.z = fmaf(wx1, fx1.z, a0.z); a0.w = fmaf(wx1, fx1.w, a0.w);
        a0.x = fmaf(wx2, fx2.x, a0.x); a0.y = fmaf(wx2, fx2.y, a0.y);
        a0.z = fmaf(wx2, fx2.z, a0.z); a0.w = fmaf(wx2, fx2.w, a0.w);
        a0.x = fmaf(wx3, fx3.x, a0.x); a0.y = fmaf(wx3, fx3.y, a0.y);
        a0.z = fmaf(wx3, fx3.z, a0.z); a0.w = fmaf(wx3, fx3.w, a0.w);
        a1.x = fmaf(wy0, fy0.x, a1.x); a1.y = fmaf(wy0, fy0.y, a1.y);
        a1.z = fmaf(wy0, fy0.z, a1.z); a1.w = fmaf(wy0, fy0.w, a1.w);
        a1.x = fmaf(wy1, fy1.x, a1.x); a1.y = fmaf(wy1, fy1.y, a1.y);
        a1.z = fmaf(wy1, fy1.z, a1.z); a1.w = fmaf(wy1, fy1.w, a1.w);
        a1.x = fmaf(wy2, fy2.x, a1.x); a1.y = fmaf(wy2, fy2.y, a1.y);
        a1.z = fmaf(wy2, fy2.z, a1.z); a1.w = fmaf(wy2, fy2.w, a1.w);
        a1.x = fmaf(wy3, fy3.x, a1.x); a1.y = fmaf(wy3, fy3.y, a1.y);
        a1.z = fmaf(wy3, fy3.z, a1.z); a1.w = fmaf(wy3, fy3.w, a1.w);
    }
    // tails
    agg_range(0, beg0 + m, end0, er0, h, co, ela, fsa, &a0, &s0);
    agg_range(1, beg1 + m, end1, er1, h, co, elb, fsb, &a1, &s1);

    const float i0 = (n0 > 0) ? (1.f / s0) : 0.f;
    const float i1 = (n1 > 0) ? (1.f / s1) : 0.f;

    float4 b0 = *(const float4*)&cb0[co];
    float4 b1 = *(const float4*)&cb1[co];
    float4 hv = *(const float4*)&h1[(size_t)d * NF + co];

    float4 o;
    o.x = fmaf(a0.x, i0, a1.x * i1) + b0.x + b1.x;
    o.y = fmaf(a0.y, i0, a1.y * i1) + b0.y + b1.y;
    o.z = fmaf(a0.z, i0, a1.z * i1) + b0.z + b1.z;
    o.w = fmaf(a0.w, i0, a1.w * i1) + b0.w + b1.w;
    o.x = (o.x > 0.f ? o.x : 0.f) + hv.x;
    o.y = (o.y > 0.f ? o.y : 0.f) + hv.y;
    o.z = (o.z > 0.f ? o.z : 0.f) + hv.z;
    o.w = (o.w > 0.f ? o.w : 0.f) + hv.w;
    *(float4*)&t_out[(size_t)d * NF + co] = o;

    // block-level BN stats (8 nodes x 128 cols)
    *(float4*)&ts[wid][co] = o;
    __syncthreads();
    if (threadIdx.x < NF) {
        int c = threadIdx.x;
        double s_a = 0.0, s_b = 0.0, q_a = 0.0, q_b = 0.0;
#pragma unroll
        for (int w = 0; w < 8; w += 2) {
            float xa = ts[w][c], xb = ts[w + 1][c];
            s_a += xa;                 s_b += xb;
            q_a += (double)xa * xa;    q_b += (double)xb * xb;
        }
        atomicAdd(&g_sum[slot][c], s_a + s_b);
        atomicAdd(&g_sq[slot][c],  q_a + q_b);
    }
}

// ---------------- normalize ----------------
#define RPB 64
__global__ void normalize128(const float* __restrict__ x, const float* __restrict__ g,
                             const float* __restrict__ b, float* __restrict__ y,
                             int do_relu, int slot) {
    int col = threadIdx.x;
    double mu = g_sum[slot][col] / (double)N_NODES;
    double var = g_sq[slot][col] / (double)N_NODES - mu * mu;
    float sc = g[col] * rsqrtf((float)var + BN_EPS);
    float sh = b[col] - (float)mu * sc;
    int r0 = blockIdx.x * RPB;
    for (int r = 0; r < RPB; r++) {
        int row = r0 + r;
        if (row >= N_NODES) break;
        float v = x[(size_t)row * NF + col] * sc + sh;
        if (do_relu) v = v > 0.f ? v : 0.f;
        y[(size_t)row * NF + col] = v;
    }
}

// ---------------- final 128 -> 16 GEMM, BN affine+relu fused in load -------
__global__ __launch_bounds__(128)
void gemm_out(const float* __restrict__ x, const float* __restrict__ clf_g,
              const float* __restrict__ clf_b, const float* __restrict__ W2,
              const float* __restrict__ b2, float* __restrict__ out, int slot) {
    __shared__ float xs[8][NF];
    int tid = threadIdx.x;
    int r0 = blockIdx.x * 8;
    double mu = g_sum[slot][tid] / (double)N_NODES;
    double var = g_sq[slot][tid] / (double)N_NODES - mu * mu;
    float sc = clf_g[tid] * rsqrtf((float)var + BN_EPS);
    float sh = clf_b[tid] - (float)mu * sc;
#pragma unroll
    for (int i = 0; i < 8; i++) {
        int row = r0 + i;
        float v = (row < N_NODES) ? fmaf(x[(size_t)row * NF + tid], sc, sh) : 0.f;
        xs[i][tid] = v > 0.f ? v : 0.f;
    }
    __syncthreads();
    int row = tid >> 4;
    int c = tid & 15;
    float acc = b2[c];
#pragma unroll 8
    for (int k = 0; k < NF; k++) acc = fmaf(xs[row][k], W2[k * 16 + c], acc);
    if (r0 + row < N_NODES) out[(size_t)(r0 + row) * 16 + c] = acc;
}

// ---------------- host ----------------
extern "C" void kernel_launch(void* const* d_in, const int* in_sizes, int n_in,
                              void* d_out, int out_size) {
    const float* feat     = (const float*)d_in[0];
    const float* fc_W     = (const float*)d_in[1];
    const float* attn_l   = (const float*)d_in[2];
    const float* attn_r   = (const float*)d_in[3];
    const float* conv_b   = (const float*)d_in[4];
    const float* skip_W   = (const float*)d_in[5];
    const float* skip_b   = (const float*)d_in[6];
    const float* norm_g   = (const float*)d_in[7];
    const float* norm_b   = (const float*)d_in[8];
    const float* clf_W1   = (const float*)d_in[9];
    const float* clf_b1   = (const float*)d_in[10];
    const float* clf_g    = (const float*)d_in[11];
    const float* clf_b    = (const float*)d_in[12];
    const float* clf_W2   = (const float*)d_in[13];
    const float* clf_b2   = (const float*)d_in[14];
    const int*   src      = (const int*)d_in[15];
    const int*   dst      = (const int*)d_in[16];
    float* out = (float*)d_out;

    float *h, *h1, *fsa, *fsb, *h2, *ela, *era, *elb, *erb;
    cudaGetSymbolAddress((void**)&h,   g_h);
    cudaGetSymbolAddress((void**)&h1,  g_h1);
    cudaGetSymbolAddress((void**)&fsa, g_fsa);
    cudaGetSymbolAddress((void**)&fsb, g_fsb);
    cudaGetSymbolAddress((void**)&h2,  g_h2);
    cudaGetSymbolAddress((void**)&ela, g_ela);
    cudaGetSymbolAddress((void**)&era, g_era);
    cudaGetSymbolAddress((void**)&elb, g_elb);
    cudaGetSymbolAddress((void**)&erb, g_erb);

    const int gemm_grid  = (N_NODES + 127) / 128;        // 391
    const int node2_grid = (2 * N_NODES + 255) / 256;
    const int edge2_grid = (2 * N_EDGES + 255) / 256;
    const int agg_grid   = N_NODES / 8;                  // 6250
    const int bn_grid    = (N_NODES + RPB - 1) / RPB;    // 782

    // lazily-created side stream + events for the CSR fork (host resources only)
    static cudaStream_t s_csr = nullptr;
    static cudaEvent_t ev_fork = nullptr, ev_join = nullptr;
    if (s_csr == nullptr) {
        cudaStreamCreate(&s_csr);
        cudaEventCreateWithFlags(&ev_fork, cudaEventDisableTiming);
        cudaEventCreateWithFlags(&ev_join, cudaEventDisableTiming);
    }

    // ---- fork: CSR build + stats zero on side stream ----
    cudaEventRecord(ev_fork, 0);
    cudaStreamWaitEvent(s_csr, ev_fork, 0);
    zero_deg_all<<<node2_grid, 256, 0, s_csr>>>();
    hist_deg_all<<<edge2_grid, 256, 0, s_csr>>>(dst);
    scan_blocks_all<<<2 * N_SCANB, SCAN_B, 0, s_csr>>>();
    scan_bsum_all<<<2, 64, 0, s_csr>>>();
    scan_finish_all<<<node2_grid, 256, 0, s_csr>>>();
    scatter_csr_all<<<edge2_grid, 256, 0, s_csr>>>(src, dst);
    cudaEventRecord(ev_join, s_csr);

    // ---- main stream: layer-1 GEMMs run concurrently with the CSR build ----
    {
        dim3 g3(gemm_grid, 3);
        gemm128x3<<<g3, 256>>>(feat,
                               skip_W, skip_b,
                               fc_W, fc_W + (size_t)NF * NF,
                               attn_l, attn_r,
                               attn_l + NF, attn_r + NF,
                               h1, fsa, fsb, ela, era, elb, erb);
    }
    cudaStreamWaitEvent(0, ev_join, 0);   // join before first CSR consumer

    for (int l = 0; l < 2; l++) {
        int lr0 = l * 2, lr1 = l * 2 + 1;
        if (l > 0) {
            dim3 g3(gemm_grid, 3);
            gemm128x3<<<g3, 256>>>(h,
                                   skip_W + l * NF * NF, skip_b + l * NF,
                                   fc_W + (size_t)lr0 * NF * NF,
                                   fc_W + (size_t)lr1 * NF * NF,
                                   attn_l + lr0 * NF, attn_r + lr0 * NF,
                                   attn_l + lr1 * NF, attn_r + lr1 * NF,
                                   h1, fsa, fsb, ela, era, elb, erb);
        }
        gat_agg2<<<agg_grid, 256>>>(ela, era, fsa, elb, erb, fsb,
                                    h1, conv_b + lr0 * NF, conv_b + lr1 * NF,
                                    h2, l);
        normalize128<<<bn_grid, 128>>>(h2, norm_g + l * NF, norm_b + l * NF, h, 0, l);
    }

    // classifier: GEMM with fused BN stats, then BN+relu fused into gemm_out
    gemm128_stats<<<gemm_grid, 256>>>(h, clf_W1, clf_b1, h1, 2);
    gemm_out<<<(N_NODES + 7) / 8, 128>>>(h1, clf_g, clf_b, clf_W2, clf_b2, out, 2);
}

// round 15
// speedup vs baseline: 1.1438x; 1.0357x over previous
#include <cuda_runtime.h>
#include <math.h>

#define N_NODES 50000
#define N_EDGES 500000
#define NF      128
#define NH      4
#define NEG_SLOPE 0.2f
#define BN_EPS 1e-5f
#define SCAN_B  1024
#define N_SCANB ((N_NODES + SCAN_B - 1) / SCAN_B)   // 49

// ---------------- scratch (device globals; no allocation allowed) ----------
__device__ float g_h  [N_NODES * NF];
__device__ float g_h1 [N_NODES * NF];
__device__ float g_fsa[N_NODES * NF];
__device__ float g_fsb[N_NODES * NF];
__device__ float g_h2 [N_NODES * NF];
__device__ float g_ela[N_NODES * NH];
__device__ float g_era[N_NODES * NH];
__device__ float g_elb[N_NODES * NH];
__device__ float g_erb[N_NODES * NH];
__device__ double g_sum[3][NF];
__device__ double g_sq [3][NF];
// CSR (2 relations)
__device__ int g_deg   [2][N_NODES];
__device__ int g_rowptr[2][N_NODES + 1];
__device__ int g_cursor[2][N_NODES];
__device__ int g_colsrc[2][N_EDGES];
__device__ int g_bsum  [2][N_SCANB];

// ---------------- CSR build (both relations in one grid) ----------------
__global__ void zero_deg_all() {      // also zeroes ALL BN stats (global index)
    int i = blockIdx.x * blockDim.x + threadIdx.x;
    if (i < 2 * N_NODES) ((int*)g_deg)[i] = 0;
    if (i < 3 * NF) {
        ((double*)g_sum)[i] = 0.0;
        ((double*)g_sq)[i]  = 0.0;
    }
}

__global__ void hist_deg_all(const int* __restrict__ dst) {   // dst = [2][E]
    int i = blockIdx.x * blockDim.x + threadIdx.x;
    if (i >= 2 * N_EDGES) return;
    int r = i / N_EDGES;
    atomicAdd(&g_deg[r][dst[i]], 1);
}

__global__ __launch_bounds__(SCAN_B)
void scan_blocks_all() {
    __shared__ int tmp[SCAN_B];
    int r  = blockIdx.x / N_SCANB;
    int bb = blockIdx.x % N_SCANB;
    int i = bb * SCAN_B + threadIdx.x;
    int v = (i < N_NODES) ? g_deg[r][i] : 0;
    tmp[threadIdx.x] = v;
    __syncthreads();
    for (int off = 1; off < SCAN_B; off <<= 1) {
        int t = (threadIdx.x >= off) ? tmp[threadIdx.x - off] : 0;
        __syncthreads();
        tmp[threadIdx.x] += t;
        __syncthreads();
    }
    if (i < N_NODES) g_rowptr[r][i] = tmp[threadIdx.x] - v;   // exclusive
    if (threadIdx.x == SCAN_B - 1) g_bsum[r][bb] = tmp[SCAN_B - 1];
}

__global__ void scan_bsum_all() {     // 2 blocks, one per relation
    __shared__ int s[64];
    int r = blockIdx.x;
    int v = (threadIdx.x < N_SCANB) ? g_bsum[r][threadIdx.x] : 0;
    s[threadIdx.x] = v;
    __syncthreads();
    for (int off = 1; off < 64; off <<= 1) {
        int t = (threadIdx.x >= off) ? s[threadIdx.x - off] : 0;
        __syncthreads();
        s[threadIdx.x] += t;
        __syncthreads();
    }
    if (threadIdx.x < N_SCANB) g_bsum[r][threadIdx.x] = s[threadIdx.x] - v;  // exclusive
}

__global__ void scan_finish_all() {
    int i = blockIdx.x * blockDim.x + threadIdx.x;
    if (i >= 2 * N_NODES) return;
    int r = i / N_NODES;
    int n = i % N_NODES;
    int v = g_rowptr[r][n] + g_bsum[r][n / SCAN_B];
    g_rowptr[r][n] = v;
    g_cursor[r][n] = v;
    if (n == 0) g_rowptr[r][N_NODES] = N_EDGES;
}

__global__ void scatter_csr_all(const int* __restrict__ src, const int* __restrict__ dst) {
    int i = blockIdx.x * blockDim.x + threadIdx.x;
    if (i >= 2 * N_EDGES) return;
    int r = i / N_EDGES;
    int p = atomicAdd(&g_cursor[r][dst[i]], 1);
    g_colsrc[r][p] = src[i];
}

// ---------------- software-pipelined SGEMM core (BK=16) ----------------
__device__ __forceinline__ void cp_async16(void* smem, const void* gmem) {
    unsigned sa = (unsigned)__cvta_generic_to_shared(smem);
    asm volatile("cp.async.cg.shared.global [%0], [%1], 16;\n"
                 :: "r"(sa), "l"(gmem));
}
__device__ __forceinline__ void cp_commit() {
    asm volatile("cp.async.commit_group;\n");
}
__device__ __forceinline__ void cp_wait0() {
    asm volatile("cp.async.wait_group 0;\n" ::: "memory");
}

// one 128-row tile of C = A@W (+bias) (+attn epilogue) (+fused BN stats)
__device__ __forceinline__ void gemm_body(
    const float* __restrict__ A, const float* __restrict__ W,
    const float* __restrict__ bias, float* __restrict__ C,
    const float* __restrict__ al, const float* __restrict__ ar,
    float* __restrict__ elo, float* __restrict__ ero,
    float As[2][16][128], float Ws[2][16][128],
    float (*psum)[NF], float (*psq)[NF], int slot) {

    const int tid = threadIdx.x;
    const int tx = tid & 15;
    const int ty = tid >> 4;
    const int rb = blockIdx.x * 128;

    const int arow  = tid >> 1;          // 0..127
    const int acol8 = (tid & 1) * 8;     // 0 or 8
    const int wrow  = tid >> 4;          // 0..15
    const int wcol8 = (tid & 15) * 8;    // 0..120
    const int gr = rb + arow;
    const bool arow_ok = (gr < N_NODES);

    float acc[8][8];
#pragma unroll
    for (int i = 0; i < 8; i++)
#pragma unroll
        for (int j = 0; j < 8; j++) acc[i][j] = 0.f;

    // prologue: tile 0 (k = 0..15)
    float4 av0 = make_float4(0.f, 0.f, 0.f, 0.f), av1 = av0;
    if (arow_ok) {
        av0 = *(const float4*)&A[(size_t)gr * NF + acol8];
        av1 = *(const float4*)&A[(size_t)gr * NF + acol8 + 4];
    }
    cp_async16(&Ws[0][wrow][wcol8],     &W[(size_t)wrow * NF + wcol8]);
    cp_async16(&Ws[0][wrow][wcol8 + 4], &W[(size_t)wrow * NF + wcol8 + 4]);
    cp_commit();
    As[0][acol8 + 0][arow] = av0.x; As[0][acol8 + 1][arow] = av0.y;
    As[0][acol8 + 2][arow] = av0.z; As[0][acol8 + 3][arow] = av0.w;
    As[0][acol8 + 4][arow] = av1.x; As[0][acol8 + 5][arow] = av1.y;
    As[0][acol8 + 6][arow] = av1.z; As[0][acol8 + 7][arow] = av1.w;
    cp_wait0();
    __syncthreads();

    int buf = 0;
    for (int t = 0; t < 8; t++) {
        const int kc = t * 16;
        const bool has_next = (t + 1 < 8);
        float4 an0, an1;
        if (has_next) {
            an0 = make_float4(0.f, 0.f, 0.f, 0.f); an1 = an0;
            if (arow_ok) {
                an0 = *(const float4*)&A[(size_t)gr * NF + kc + 16 + acol8];
                an1 = *(const float4*)&A[(size_t)gr * NF + kc + 16 + acol8 + 4];
            }
            cp_async16(&Ws[buf ^ 1][wrow][wcol8],
                       &W[(size_t)(kc + 16 + wrow) * NF + wcol8]);
            cp_async16(&Ws[buf ^ 1][wrow][wcol8 + 4],
                       &W[(size_t)(kc + 16 + wrow) * NF + wcol8 + 4]);
            cp_commit();
        }

#pragma unroll
        for (int kk = 0; kk < 16; kk++) {
            float a[8], b[8];
            *(float4*)&a[0] = *(float4*)&As[buf][kk][ty * 8];
            *(float4*)&a[4] = *(float4*)&As[buf][kk][ty * 8 + 4];
            *(float4*)&b[0] = *(float4*)&Ws[buf][kk][tx * 8];
            *(float4*)&b[4] = *(float4*)&Ws[buf][kk][tx * 8 + 4];
#pragma unroll
            for (int i = 0; i < 8; i++)
#pragma unroll
                for (int j = 0; j < 8; j++)
                    acc[i][j] = fmaf(a[i], b[j], acc[i][j]);
        }

        if (has_next) {
            As[buf ^ 1][acol8 + 0][arow] = an0.x; As[buf ^ 1][acol8 + 1][arow] = an0.y;
            As[buf ^ 1][acol8 + 2][arow] = an0.z; As[buf ^ 1][acol8 + 3][arow] = an0.w;
            As[buf ^ 1][acol8 + 4][arow] = an1.x; As[buf ^ 1][acol8 + 5][arow] = an1.y;
            As[buf ^ 1][acol8 + 6][arow] = an1.z; As[buf ^ 1][acol8 + 7][arow] = an1.w;
            cp_wait0();
        }
        __syncthreads();
        buf ^= 1;
    }

    const int cb = tx * 8;
    float bcol[8];
#pragma unroll
    for (int j = 0; j < 8; j++) bcol[j] = bias ? bias[cb + j] : 0.f;
    float alv[8], arv[8];
    if (elo) {
#pragma unroll
        for (int j = 0; j < 8; j++) { alv[j] = al[cb + j]; arv[j] = ar[cb + j]; }
    }
    const int hh = tx >> 2;

    float ps[8], pq[8];
    if (psum) {
#pragma unroll
        for (int j = 0; j < 8; j++) { ps[j] = 0.f; pq[j] = 0.f; }
    }

#pragma unroll
    for (int i = 0; i < 8; i++) {
        int row = rb + ty * 8 + i;
        if (row < N_NODES) {
            float v0 = acc[i][0] + bcol[0], v1 = acc[i][1] + bcol[1];
            float v2 = acc[i][2] + bcol[2], v3 = acc[i][3] + bcol[3];
            float v4 = acc[i][4] + bcol[4], v5 = acc[i][5] + bcol[5];
            float v6 = acc[i][6] + bcol[6], v7 = acc[i][7] + bcol[7];
            *(float4*)&C[(size_t)row * NF + cb]     = make_float4(v0, v1, v2, v3);
            *(float4*)&C[(size_t)row * NF + cb + 4] = make_float4(v4, v5, v6, v7);
            if (psum) {
                ps[0] += v0; pq[0] += v0 * v0; ps[1] += v1; pq[1] += v1 * v1;
                ps[2] += v2; pq[2] += v2 * v2; ps[3] += v3; pq[3] += v3 * v3;
                ps[4] += v4; pq[4] += v4 * v4; ps[5] += v5; pq[5] += v5 * v5;
                ps[6] += v6; pq[6] += v6 * v6; ps[7] += v7; pq[7] += v7 * v7;
            }
        }
        if (elo) {
            float p = 0.f, q = 0.f;
#pragma unroll
            for (int j = 0; j < 8; j++) {
                p = fmaf(acc[i][j], alv[j], p);
                q = fmaf(acc[i][j], arv[j], q);
            }
            p += __shfl_down_sync(0xffffffffu, p, 1, 4);
            p += __shfl_down_sync(0xffffffffu, p, 2, 4);
            q += __shfl_down_sync(0xffffffffu, q, 1, 4);
            q += __shfl_down_sync(0xffffffffu, q, 2, 4);
            if ((tx & 3) == 0 && row < N_NODES) {
                elo[row * NH + hh] = p;
                ero[row * NH + hh] = q;
            }
        }
    }

    if (psum) {
#pragma unroll
        for (int j = 0; j < 8; j++) { psum[ty][cb + j] = ps[j]; psq[ty][cb + j] = pq[j]; }
        __syncthreads();
        if (tid < NF) {
            double s = 0.0, q = 0.0;
#pragma unroll
            for (int g = 0; g < 16; g++) { s += (double)psum[g][tid]; q += (double)psq[g][tid]; }
            atomicAdd(&g_sum[slot][tid], s);
            atomicAdd(&g_sq[slot][tid], q);
        }
    }
}

// classifier GEMM with fused BN stats
__global__ __launch_bounds__(256, 2)
void gemm128_stats(const float* __restrict__ A, const float* __restrict__ W,
                   const float* __restrict__ bias, float* __restrict__ C, int slot) {
    __shared__ float As[2][16][128];
    __shared__ float Ws[2][16][128];
    __shared__ float psum[16][NF];
    __shared__ float psq[16][NF];
    gemm_body(A, W, bias, C, nullptr, nullptr, nullptr, nullptr, As, Ws, psum, psq, slot);
}

// batched tri-GEMM: blockIdx.y = 0 skip, 1 fc0(+attn), 2 fc1(+attn)
__global__ __launch_bounds__(256, 2)
void gemm128x3(const float* __restrict__ A,
               const float* __restrict__ Wskip, const float* __restrict__ bskip,
               const float* __restrict__ Wfc0, const float* __restrict__ Wfc1,
               const float* __restrict__ al0, const float* __restrict__ ar0,
               const float* __restrict__ al1, const float* __restrict__ ar1,
               float* __restrict__ Cskip, float* __restrict__ Cfc0,
               float* __restrict__ Cfc1,
               float* __restrict__ el0, float* __restrict__ er0,
               float* __restrict__ el1, float* __restrict__ er1) {
    __shared__ float As[2][16][128];
    __shared__ float Ws[2][16][128];
    if (blockIdx.y == 0) {
        gemm_body(A, Wskip, bskip, Cskip, nullptr, nullptr, nullptr, nullptr, As, Ws,
                  nullptr, nullptr, 0);
    } else if (blockIdx.y == 1) {
        gemm_body(A, Wfc0, nullptr, Cfc0, al0, ar0, el0, er0, As, Ws, nullptr, nullptr, 0);
    } else {
        gemm_body(A, Wfc1, nullptr, Cfc1, al1, ar1, el1, er1, As, Ws, nullptr, nullptr, 0);
    }
}

// ---------------- fused dual-relation GAT agg + finalize + BN stats --------
// (R11 version: sequential relations, x4 unroll + index prefetch)
__device__ __forceinline__ float agg_one_rel(
    int r, int d, int h, int co,
    const float* __restrict__ el, const float* __restrict__ er,
    const float* __restrict__ fs, float4* acc_out) {
    const int beg = g_rowptr[r][d];
    const int end = g_rowptr[r][d + 1];
    const float er_h = er[d * NH + h];
    float4 acc = make_float4(0.f, 0.f, 0.f, 0.f);
    float sh = 0.f;
    const int n4 = (end - beg) >> 2;
    int s0 = 0, s1 = 0, s2 = 0, s3 = 0;
    if (n4 > 0) {
        s0 = g_colsrc[r][beg];     s1 = g_colsrc[r][beg + 1];
        s2 = g_colsrc[r][beg + 2]; s3 = g_colsrc[r][beg + 3];
    }
    for (int it = 0; it < n4; it++) {
        int t0 = s0, t1 = s1, t2 = s2, t3 = s3;
        int nb = beg + (it + 1) * 4;
        if (it + 1 < n4) {                    // prefetch next quad of indices
            s0 = g_colsrc[r][nb];     s1 = g_colsrc[r][nb + 1];
            s2 = g_colsrc[r][nb + 2]; s3 = g_colsrc[r][nb + 3];
        }
        float el0 = el[t0 * NH + h];
        float el1 = el[t1 * NH + h];
        float el2 = el[t2 * NH + h];
        float el3 = el[t3 * NH + h];
        float4 f0 = *(const float4*)&fs[(size_t)t0 * NF + co];
        float4 f1 = *(const float4*)&fs[(size_t)t1 * NF + co];
        float4 f2 = *(const float4*)&fs[(size_t)t2 * NF + co];
        float4 f3 = *(const float4*)&fs[(size_t)t3 * NF + co];
        float v0 = el0 + er_h; v0 = v0 > 0.f ? v0 : NEG_SLOPE * v0;
        float v1 = el1 + er_h; v1 = v1 > 0.f ? v1 : NEG_SLOPE * v1;
        float v2 = el2 + er_h; v2 = v2 > 0.f ? v2 : NEG_SLOPE * v2;
        float v3 = el3 + er_h; v3 = v3 > 0.f ? v3 : NEG_SLOPE * v3;
        float w0 = expf(v0), w1 = expf(v1), w2 = expf(v2), w3 = expf(v3);
        sh += (w0 + w1) + (w2 + w3);
        acc.x = fmaf(w0, f0.x, acc.x); acc.y = fmaf(w0, f0.y, acc.y);
        acc.z = fmaf(w0, f0.z, acc.z); acc.w = fmaf(w0, f0.w, acc.w);
        acc.x = fmaf(w1, f1.x, acc.x); acc.y = fmaf(w1, f1.y, acc.y);
        acc.z = fmaf(w1, f1.z, acc.z); acc.w = fmaf(w1, f1.w, acc.w);
        acc.x = fmaf(w2, f2.x, acc.x); acc.y = fmaf(w2, f2.y, acc.y);
        acc.z = fmaf(w2, f2.z, acc.z); acc.w = fmaf(w2, f2.w, acc.w);
        acc.x = fmaf(w3, f3.x, acc.x); acc.y = fmaf(w3, f3.y, acc.y);
        acc.z = fmaf(w3, f3.z, acc.z); acc.w = fmaf(w3, f3.w, acc.w);
    }
    for (int e = beg + n4 * 4; e < end; e++) {
        int s = g_colsrc[r][e];
        float elA = el[s * NH + h];
        float4 fa = *(const float4*)&fs[(size_t)s * NF + co];
        float vA = elA + er_h; vA = vA > 0.f ? vA : NEG_SLOPE * vA;
        float wA = expf(vA);
        sh += wA;
        acc.x = fmaf(wA, fa.x, acc.x); acc.y = fmaf(wA, fa.y, acc.y);
        acc.z = fmaf(wA, fa.z, acc.z); acc.w = fmaf(wA, fa.w, acc.w);
    }
    *acc_out = acc;
    return (end > beg) ? (1.f / sh) : 0.f;
}

__global__ __launch_bounds__(256)
void gat_agg2(const float* __restrict__ ela, const float* __restrict__ era,
              const float* __restrict__ fsa,
              const float* __restrict__ elb, const float* __restrict__ erb,
              const float* __restrict__ fsb,
              const float* __restrict__ h1,
              const float* __restrict__ cb0, const float* __restrict__ cb1,
              float* __restrict__ t_out, int slot) {
    __shared__ float ts[8][NF];
    const int wid = threadIdx.x >> 5;
    const int lane = threadIdx.x & 31;
    const int d = blockIdx.x * 8 + wid;        // grid = 6250 -> 50000 warps
    const int h = lane >> 3;
    const int co = lane * 4;

    float4 a0, a1;
    float i0 = agg_one_rel(0, d, h, co, ela, era, fsa, &a0);
    float i1 = agg_one_rel(1, d, h, co, elb, erb, fsb, &a1);

    float4 b0 = *(const float4*)&cb0[co];
    float4 b1 = *(const float4*)&cb1[co];
    float4 hv = *(const float4*)&h1[(size_t)d * NF + co];

    float4 v;
    v.x = fmaf(a0.x, i0, a1.x * i1) + b0.x + b1.x;
    v.y = fmaf(a0.y, i0, a1.y * i1) + b0.y + b1.y;
    v.z = fmaf(a0.z, i0, a1.z * i1) + b0.z + b1.z;
    v.w = fmaf(a0.w, i0, a1.w * i1) + b0.w + b1.w;
    v.x = (v.x > 0.f ? v.x : 0.f) + hv.x;
    v.y = (v.y > 0.f ? v.y : 0.f) + hv.y;
    v.z = (v.z > 0.f ? v.z : 0.f) + hv.z;
    v.w = (v.w > 0.f ? v.w : 0.f) + hv.w;
    *(float4*)&t_out[(size_t)d * NF + co] = v;

    // block-level BN stats (8 nodes x 128 cols)
    *(float4*)&ts[wid][co] = v;
    __syncthreads();
    if (threadIdx.x < NF) {
        int c = threadIdx.x;
        double s_a = 0.0, s_b = 0.0, q_a = 0.0, q_b = 0.0;
#pragma unroll
        for (int w = 0; w < 8; w += 2) {
            float xa = ts[w][c], xb = ts[w + 1][c];
            s_a += xa;                 s_b += xb;
            q_a += (double)xa * xa;    q_b += (double)xb * xb;
        }
        atomicAdd(&g_sum[slot][c], s_a + s_b);
        atomicAdd(&g_sq[slot][c],  q_a + q_b);
    }
}

// ---------------- normalize ----------------
#define RPB 64
__global__ void normalize128(const float* __restrict__ x, const float* __restrict__ g,
                             const float* __restrict__ b, float* __restrict__ y,
                             int do_relu, int slot) {
    int col = threadIdx.x;
    double mu = g_sum[slot][col] / (double)N_NODES;
    double var = g_sq[slot][col] / (double)N_NODES - mu * mu;
    float sc = g[col] * rsqrtf((float)var + BN_EPS);
    float sh = b[col] - (float)mu * sc;
    int r0 = blockIdx.x * RPB;
    for (int r = 0; r < RPB; r++) {
        int row = r0 + r;
        if (row >= N_NODES) break;
        float v = x[(size_t)row * NF + col] * sc + sh;
        if (do_relu) v = v > 0.f ? v : 0.f;
        y[(size_t)row * NF + col] = v;
    }
}

// ---------------- final 128 -> 16 GEMM, BN affine+relu fused in load -------
// 256 threads, 16 rows per block
__global__ __launch_bounds__(256)
void gemm_out(const float* __restrict__ x, const float* __restrict__ clf_g,
              const float* __restrict__ clf_b, const float* __restrict__ W2,
              const float* __restrict__ b2, float* __restrict__ out, int slot) {
    __shared__ float xs[16][NF];
    int tid = threadIdx.x;
    int col = tid & 127;
    int half = tid >> 7;                 // 0 or 1 -> rows 0..7 / 8..15
    int r0 = blockIdx.x * 16;
    double mu = g_sum[slot][col] / (double)N_NODES;
    double var = g_sq[slot][col] / (double)N_NODES - mu * mu;
    float sc = clf_g[col] * rsqrtf((float)var + BN_EPS);
    float sh = clf_b[col] - (float)mu * sc;
#pragma unroll
    for (int i = 0; i < 8; i++) {
        int row = r0 + half * 8 + i;
        float v = (row < N_NODES) ? fmaf(x[(size_t)row * NF + col], sc, sh) : 0.f;
        xs[half * 8 + i][col] = v > 0.f ? v : 0.f;
    }
    __syncthreads();
    int row = tid >> 4;                  // 0..15
    int c = tid & 15;
    float acc = b2[c];
#pragma unroll 8
    for (int k = 0; k < NF; k++) acc = fmaf(xs[row][k], W2[k * 16 + c], acc);
    if (r0 + row < N_NODES) out[(size_t)(r0 + row) * 16 + c] = acc;
}

// ---------------- host ----------------
extern "C" void kernel_launch(void* const* d_in, const int* in_sizes, int n_in,
                              void* d_out, int out_size) {
    const float* feat     = (const float*)d_in[0];
    const float* fc_W     = (const float*)d_in[1];
    const float* attn_l   = (const float*)d_in[2];
    const float* attn_r   = (const float*)d_in[3];
    const float* conv_b   = (const float*)d_in[4];
    const float* skip_W   = (const float*)d_in[5];
    const float* skip_b   = (const float*)d_in[6];
    const float* norm_g   = (const float*)d_in[7];
    const float* norm_b   = (const float*)d_in[8];
    const float* clf_W1   = (const float*)d_in[9];
    const float* clf_b1   = (const float*)d_in[10];
    const float* clf_g    = (const float*)d_in[11];
    const float* clf_b    = (const float*)d_in[12];
    const float* clf_W2   = (const float*)d_in[13];
    const float* clf_b2   = (const float*)d_in[14];
    const int*   src      = (const int*)d_in[15];
    const int*   dst      = (const int*)d_in[16];
    float* out = (float*)d_out;

    float *h, *h1, *fsa, *fsb, *h2, *ela, *era, *elb, *erb;
    cudaGetSymbolAddress((void**)&h,   g_h);
    cudaGetSymbolAddress((void**)&h1,  g_h1);
    cudaGetSymbolAddress((void**)&fsa, g_fsa);
    cudaGetSymbolAddress((void**)&fsb, g_fsb);
    cudaGetSymbolAddress((void**)&h2,  g_h2);
    cudaGetSymbolAddress((void**)&ela, g_ela);
    cudaGetSymbolAddress((void**)&era, g_era);
    cudaGetSymbolAddress((void**)&elb, g_elb);
    cudaGetSymbolAddress((void**)&erb, g_erb);

    const int gemm_grid  = (N_NODES + 127) / 128;        // 391
    const int node2_grid = (2 * N_NODES + 255) / 256;
    const int edge2_grid = (2 * N_EDGES + 255) / 256;
    const int agg_grid   = N_NODES / 8;                  // 6250
    const int bn_grid    = (N_NODES + RPB - 1) / RPB;    // 782

    // lazily-created side stream + events for the CSR fork (host resources only)
    static cudaStream_t s_csr = nullptr;
    static cudaEvent_t ev_fork = nullptr, ev_join = nullptr;
    if (s_csr == nullptr) {
        cudaStreamCreate(&s_csr);
        cudaEventCreateWithFlags(&ev_fork, cudaEventDisableTiming);
        cudaEventCreateWithFlags(&ev_join, cudaEventDisableTiming);
    }

    // ---- fork: CSR build + stats zero on side stream ----
    cudaEventRecord(ev_fork, 0);
    cudaStreamWaitEvent(s_csr, ev_fork, 0);
    zero_deg_all<<<node2_grid, 256, 0, s_csr>>>();
    hist_deg_all<<<edge2_grid, 256, 0, s_csr>>>(dst);
    scan_blocks_all<<<2 * N_SCANB, SCAN_B, 0, s_csr>>>();
    scan_bsum_all<<<2, 64, 0, s_csr>>>();
    scan_finish_all<<<node2_grid, 256, 0, s_csr>>>();
    scatter_csr_all<<<edge2_grid, 256, 0, s_csr>>>(src, dst);
    cudaEventRecord(ev_join, s_csr);

    // ---- main stream: layer-1 GEMMs run concurrently with the CSR build ----
    {
        dim3 g3(gemm_grid, 3);
        gemm128x3<<<g3, 256>>>(feat,
                               skip_W, skip_b,
                               fc_W, fc_W + (size_t)NF * NF,
                               attn_l, attn_r,
                               attn_l + NF, attn_r + NF,
                               h1, fsa, fsb, ela, era, elb, erb);
    }
    cudaStreamWaitEvent(0, ev_join, 0);   // join before first CSR consumer

    for (int l = 0; l < 2; l++) {
        int lr0 = l * 2, lr1 = l * 2 + 1;
        if (l > 0) {
            dim3 g3(gemm_grid, 3);
            gemm128x3<<<g3, 256>>>(h,
                                   skip_W + l * NF * NF, skip_b + l * NF,
                                   fc_W + (size_t)lr0 * NF * NF,
                                   fc_W + (size_t)lr1 * NF * NF,
                                   attn_l + lr0 * NF, attn_r + lr0 * NF,
                                   attn_l + lr1 * NF, attn_r + lr1 * NF,
                                   h1, fsa, fsb, ela, era, elb, erb);
        }
        gat_agg2<<<agg_grid, 256>>>(ela, era, fsa, elb, erb, fsb,
                                    h1, conv_b + lr0 * NF, conv_b + lr1 * NF,
                                    h2, l);
        normalize128<<<bn_grid, 128>>>(h2, norm_g + l * NF, norm_b + l * NF, h, 0, l);
    }

    // classifier: GEMM with fused BN stats, then BN+relu fused into gemm_out
    gemm128_stats<<<gemm_grid, 256>>>(h, clf_W1, clf_b1, h1, 2);
    gemm_out<<<(N_NODES + 15) / 16, 256>>>(h1, clf_g, clf_b, clf_W2, clf_b2, out, 2);
}

// round 17
// speedup vs baseline: 1.1776x; 1.0296x over previous
#include <cuda_runtime.h>
#include <math.h>

#define N_NODES 50000
#define N_EDGES 500000
#define NF      128
#define NH      4
#define NEG_SLOPE 0.2f
#define BN_EPS 1e-5f
#define SCAN_B  1024
#define N_SCANB ((N_NODES + SCAN_B - 1) / SCAN_B)   // 49

// ---------------- scratch (device globals; no allocation allowed) ----------
__device__ float g_h1 [N_NODES * NF];
__device__ float g_fsa[N_NODES * NF];
__device__ float g_fsb[N_NODES * NF];
__device__ float g_h2 [N_NODES * NF];   // t (pre-norm activation), reused per layer
__device__ float g_ela[N_NODES * NH];
__device__ float g_era[N_NODES * NH];
__device__ float g_elb[N_NODES * NH];
__device__ float g_erb[N_NODES * NH];
__device__ double g_sum[3][NF];
__device__ double g_sq [3][NF];
// CSR (2 relations)
__device__ int g_deg   [2][N_NODES];
__device__ int g_rowptr[2][N_NODES + 1];
__device__ int g_cursor[2][N_NODES];
__device__ int g_colsrc[2][N_EDGES];
__device__ int g_bsum  [2][N_SCANB];

// ---------------- CSR build (both relations in one grid) ----------------
__global__ void zero_deg_all() {      // also zeroes ALL BN stats (global index)
    int i = blockIdx.x * blockDim.x + threadIdx.x;
    if (i < 2 * N_NODES) ((int*)g_deg)[i] = 0;
    if (i < 3 * NF) {
        ((double*)g_sum)[i] = 0.0;
        ((double*)g_sq)[i]  = 0.0;
    }
}

__global__ void hist_deg_all(const int* __restrict__ dst) {   // dst = [2][E]
    int i = blockIdx.x * blockDim.x + threadIdx.x;
    if (i >= 2 * N_EDGES) return;
    int r = i / N_EDGES;
    atomicAdd(&g_deg[r][dst[i]], 1);
}

__global__ __launch_bounds__(SCAN_B)
void scan_blocks_all() {
    __shared__ int tmp[SCAN_B];
    int r  = blockIdx.x / N_SCANB;
    int bb = blockIdx.x % N_SCANB;
    int i = bb * SCAN_B + threadIdx.x;
    int v = (i < N_NODES) ? g_deg[r][i] : 0;
    tmp[threadIdx.x] = v;
    __syncthreads();
    for (int off = 1; off < SCAN_B; off <<= 1) {
        int t = (threadIdx.x >= off) ? tmp[threadIdx.x - off] : 0;
        __syncthreads();
        tmp[threadIdx.x] += t;
        __syncthreads();
    }
    if (i < N_NODES) g_rowptr[r][i] = tmp[threadIdx.x] - v;   // exclusive
    if (threadIdx.x == SCAN_B - 1) g_bsum[r][bb] = tmp[SCAN_B - 1];
}

__global__ void scan_bsum_all() {     // 2 blocks, one per relation
    __shared__ int s[64];
    int r = blockIdx.x;
    int v = (threadIdx.x < N_SCANB) ? g_bsum[r][threadIdx.x] : 0;
    s[threadIdx.x] = v;
    __syncthreads();
    for (int off = 1; off < 64; off <<= 1) {
        int t = (threadIdx.x >= off) ? s[threadIdx.x - off] : 0;
        __syncthreads();
        s[threadIdx.x] += t;
        __syncthreads();
    }
    if (threadIdx.x < N_SCANB) g_bsum[r][threadIdx.x] = s[threadIdx.x] - v;  // exclusive
}

__global__ void scan_finish_all() {
    int i = blockIdx.x * blockDim.x + threadIdx.x;
    if (i >= 2 * N_NODES) return;
    int r = i / N_NODES;
    int n = i % N_NODES;
    int v = g_rowptr[r][n] + g_bsum[r][n / SCAN_B];
    g_rowptr[r][n] = v;
    g_cursor[r][n] = v;
    if (n == 0) g_rowptr[r][N_NODES] = N_EDGES;
}

__global__ void scatter_csr_all(const int* __restrict__ src, const int* __restrict__ dst) {
    int i = blockIdx.x * blockDim.x + threadIdx.x;
    if (i >= 2 * N_EDGES) return;
    int r = i / N_EDGES;
    int p = atomicAdd(&g_cursor[r][dst[i]], 1);
    g_colsrc[r][p] = src[i];
}

// ---------------- software-pipelined SGEMM core (BK=16, optional BN-in) ----
__device__ __forceinline__ void cp_async16(void* smem, const void* gmem) {
    unsigned sa = (unsigned)__cvta_generic_to_shared(smem);
    asm volatile("cp.async.cg.shared.global [%0], [%1], 16;\n"
                 :: "r"(sa), "l"(gmem));
}
__device__ __forceinline__ void cp_commit() {
    asm volatile("cp.async.commit_group;\n");
}
__device__ __forceinline__ void cp_wait0() {
    asm volatile("cp.async.wait_group 0;\n" ::: "memory");
}

// one 128-row tile of C = norm(A)@W (+bias) (+attn epilogue) (+fused BN stats)
// aff_slot >= 0: A' = A*sc + sh with sc/sh computed from g_sum/g_sq[aff_slot]
// and ng/nb (gamma/beta), staged in smem once per block.
// do_stats: epilogue stages BN stats, ALIASED into As/Ws (dead after mainloop).
__device__ __forceinline__ void gemm_body(
    const float* __restrict__ A, const float* __restrict__ W,
    const float* __restrict__ bias, float* __restrict__ C,
    const float* __restrict__ al, const float* __restrict__ ar,
    float* __restrict__ elo, float* __restrict__ ero,
    float As[2][16][128], float Ws[2][16][128],
    float* s_sc, float* s_sh,
    int aff_slot, const float* __restrict__ ng, const float* __restrict__ nb,
    bool do_stats, int stats_slot) {

    const int tid = threadIdx.x;
    const int tx = tid & 15;
    const int ty = tid >> 4;
    const int rb = blockIdx.x * 128;

    const int arow  = tid >> 1;          // 0..127
    const int acol8 = (tid & 1) * 8;     // 0 or 8
    const int wrow  = tid >> 4;          // 0..15
    const int wcol8 = (tid & 15) * 8;    // 0..120
    const int gr = rb + arow;
    const bool arow_ok = (gr < N_NODES);
    const bool do_aff = (aff_slot >= 0);

    if (do_aff) {
        if (tid < NF) {
            double mu = g_sum[aff_slot][tid] / (double)N_NODES;
            double var = g_sq[aff_slot][tid] / (double)N_NODES - mu * mu;
            float sc = ng[tid] * rsqrtf((float)var + BN_EPS);
            s_sc[tid] = sc;
            s_sh[tid] = nb[tid] - (float)mu * sc;
        }
        __syncthreads();
    }

    float acc[8][8];
#pragma unroll
    for (int i = 0; i < 8; i++)
#pragma unroll
        for (int j = 0; j < 8; j++) acc[i][j] = 0.f;

    // prologue: tile 0 (k = 0..15)
    float4 av0 = make_float4(0.f, 0.f, 0.f, 0.f), av1 = av0;
    if (arow_ok) {
        av0 = *(const float4*)&A[(size_t)gr * NF + acol8];
        av1 = *(const float4*)&A[(size_t)gr * NF + acol8 + 4];
    }
    cp_async16(&Ws[0][wrow][wcol8],     &W[(size_t)wrow * NF + wcol8]);
    cp_async16(&Ws[0][wrow][wcol8 + 4], &W[(size_t)wrow * NF + wcol8 + 4]);
    cp_commit();
    if (do_aff) {
        av0.x = fmaf(av0.x, s_sc[acol8 + 0], s_sh[acol8 + 0]);
        av0.y = fmaf(av0.y, s_sc[acol8 + 1], s_sh[acol8 + 1]);
        av0.z = fmaf(av0.z, s_sc[acol8 + 2], s_sh[acol8 + 2]);
        av0.w = fmaf(av0.w, s_sc[acol8 + 3], s_sh[acol8 + 3]);
        av1.x = fmaf(av1.x, s_sc[acol8 + 4], s_sh[acol8 + 4]);
        av1.y = fmaf(av1.y, s_sc[acol8 + 5], s_sh[acol8 + 5]);
        av1.z = fmaf(av1.z, s_sc[acol8 + 6], s_sh[acol8 + 6]);
        av1.w = fmaf(av1.w, s_sc[acol8 + 7], s_sh[acol8 + 7]);
    }
    As[0][acol8 + 0][arow] = av0.x; As[0][acol8 + 1][arow] = av0.y;
    As[0][acol8 + 2][arow] = av0.z; As[0][acol8 + 3][arow] = av0.w;
    As[0][acol8 + 4][arow] = av1.x; As[0][acol8 + 5][arow] = av1.y;
    As[0][acol8 + 6][arow] = av1.z; As[0][acol8 + 7][arow] = av1.w;
    cp_wait0();
    __syncthreads();

    int buf = 0;
    for (int t = 0; t < 8; t++) {
        const int kc = t * 16;
        const bool has_next = (t + 1 < 8);
        float4 an0, an1;
        if (has_next) {
            an0 = make_float4(0.f, 0.f, 0.f, 0.f); an1 = an0;
            if (arow_ok) {
                an0 = *(const float4*)&A[(size_t)gr * NF + kc + 16 + acol8];
                an1 = *(const float4*)&A[(size_t)gr * NF + kc + 16 + acol8 + 4];
            }
            cp_async16(&Ws[buf ^ 1][wrow][wcol8],
                       &W[(size_t)(kc + 16 + wrow) * NF + wcol8]);
            cp_async16(&Ws[buf ^ 1][wrow][wcol8 + 4],
                       &W[(size_t)(kc + 16 + wrow) * NF + wcol8 + 4]);
            cp_commit();
        }

#pragma unroll
        for (int kk = 0; kk < 16; kk++) {
            float a[8], b[8];
            *(float4*)&a[0] = *(float4*)&As[buf][kk][ty * 8];
            *(float4*)&a[4] = *(float4*)&As[buf][kk][ty * 8 + 4];
            *(float4*)&b[0] = *(float4*)&Ws[buf][kk][tx * 8];
            *(float4*)&b[4] = *(float4*)&Ws[buf][kk][tx * 8 + 4];
#pragma unroll
            for (int i = 0; i < 8; i++)
#pragma unroll
                for (int j = 0; j < 8; j++)
                    acc[i][j] = fmaf(a[i], b[j], acc[i][j]);
        }

        if (has_next) {
            if (do_aff) {
                const int kb = kc + 16 + acol8;
                an0.x = fmaf(an0.x, s_sc[kb + 0], s_sh[kb + 0]);
                an0.y = fmaf(an0.y, s_sc[kb + 1], s_sh[kb + 1]);
                an0.z = fmaf(an0.z, s_sc[kb + 2], s_sh[kb + 2]);
                an0.w = fmaf(an0.w, s_sc[kb + 3], s_sh[kb + 3]);
                an1.x = fmaf(an1.x, s_sc[kb + 4], s_sh[kb + 4]);
                an1.y = fmaf(an1.y, s_sc[kb + 5], s_sh[kb + 5]);
                an1.z = fmaf(an1.z, s_sc[kb + 6], s_sh[kb + 6]);
                an1.w = fmaf(an1.w, s_sc[kb + 7], s_sh[kb + 7]);
            }
            As[buf ^ 1][acol8 + 0][arow] = an0.x; As[buf ^ 1][acol8 + 1][arow] = an0.y;
            As[buf ^ 1][acol8 + 2][arow] = an0.z; As[buf ^ 1][acol8 + 3][arow] = an0.w;
            As[buf ^ 1][acol8 + 4][arow] = an1.x; As[buf ^ 1][acol8 + 5][arow] = an1.y;
            As[buf ^ 1][acol8 + 6][arow] = an1.z; As[buf ^ 1][acol8 + 7][arow] = an1.w;
            cp_wait0();
        }
        __syncthreads();
        buf ^= 1;
    }

    const int cb = tx * 8;
    float bcol[8];
#pragma unroll
    for (int j = 0; j < 8; j++) bcol[j] = bias ? bias[cb + j] : 0.f;
    float alv[8], arv[8];
    if (elo) {
#pragma unroll
        for (int j = 0; j < 8; j++) { alv[j] = al[cb + j]; arv[j] = ar[cb + j]; }
    }
    const int hh = tx >> 2;

    float ps[8], pq[8];
    if (do_stats) {
#pragma unroll
        for (int j = 0; j < 8; j++) { ps[j] = 0.f; pq[j] = 0.f; }
    }

#pragma unroll
    for (int i = 0; i < 8; i++) {
        int row = rb + ty * 8 + i;
        if (row < N_NODES) {
            float v0 = acc[i][0] + bcol[0], v1 = acc[i][1] + bcol[1];
            float v2 = acc[i][2] + bcol[2], v3 = acc[i][3] + bcol[3];
            float v4 = acc[i][4] + bcol[4], v5 = acc[i][5] + bcol[5];
            float v6 = acc[i][6] + bcol[6], v7 = acc[i][7] + bcol[7];
            *(float4*)&C[(size_t)row * NF + cb]     = make_float4(v0, v1, v2, v3);
            *(float4*)&C[(size_t)row * NF + cb + 4] = make_float4(v4, v5, v6, v7);
            if (do_stats) {
                ps[0] += v0; pq[0] += v0 * v0; ps[1] += v1; pq[1] += v1 * v1;
                ps[2] += v2; pq[2] += v2 * v2; ps[3] += v3; pq[3] += v3 * v3;
                ps[4] += v4; pq[4] += v4 * v4; ps[5] += v5; pq[5] += v5 * v5;
                ps[6] += v6; pq[6] += v6 * v6; ps[7] += v7; pq[7] += v7 * v7;
            }
        }
        if (elo) {
            float p = 0.f, q = 0.f;
#pragma unroll
            for (int j = 0; j < 8; j++) {
                p = fmaf(acc[i][j], alv[j], p);
                q = fmaf(acc[i][j], arv[j], q);
            }
            p += __shfl_down_sync(0xffffffffu, p, 1, 4);
            p += __shfl_down_sync(0xffffffffu, p, 2, 4);
            q += __shfl_down_sync(0xffffffffu, q, 1, 4);
            q += __shfl_down_sync(0xffffffffu, q, 2, 4);
            if ((tx & 3) == 0 && row < N_NODES) {
                elo[row * NH + hh] = p;
                ero[row * NH + hh] = q;
            }
        }
    }

    if (do_stats) {
        // alias the (dead) As/Ws k-loop buffers as stats staging: each is 16KB,
        // psum/psq each need 16*128*4 = 8KB. Ordered by the final mainloop barrier.
        float (*psum)[NF] = (float (*)[NF])&As[0][0][0];
        float (*psq)[NF]  = (float (*)[NF])&Ws[0][0][0];
        __syncthreads();   // all warps done reading As/Ws before reuse
#pragma unroll
        for (int j = 0; j < 8; j++) { psum[ty][cb + j] = ps[j]; psq[ty][cb + j] = pq[j]; }
        __syncthreads();
        if (tid < NF) {
            double s = 0.0, q = 0.0;
#pragma unroll
            for (int g = 0; g < 16; g++) { s += (double)psum[g][tid]; q += (double)psq[g][tid]; }
            atomicAdd(&g_sum[stats_slot][tid], s);
            atomicAdd(&g_sq[stats_slot][tid], q);
        }
    }
}

// classifier GEMM: BN-affine(slot) on input + fused output BN stats
__global__ __launch_bounds__(256, 2)
void gemm128_stats(const float* __restrict__ A, const float* __restrict__ W,
                   const float* __restrict__ bias, float* __restrict__ C,
                   int aff_slot, const float* __restrict__ ng,
                   const float* __restrict__ nb, int stats_slot) {
    __shared__ float As[2][16][128];
    __shared__ float Ws[2][16][128];
    __shared__ float s_sc[NF], s_sh[NF];
    gemm_body(A, W, bias, C, nullptr, nullptr, nullptr, nullptr, As, Ws,
              s_sc, s_sh, aff_slot, ng, nb, true, stats_slot);
}

// batched tri-GEMM: blockIdx.y = 0 skip, 1 fc0(+attn), 2 fc1(+attn);
// optional BN-affine on shared input A
__global__ __launch_bounds__(256, 2)
void gemm128x3(const float* __restrict__ A,
               const float* __restrict__ Wskip, const float* __restrict__ bskip,
               const float* __restrict__ Wfc0, const float* __restrict__ Wfc1,
               const float* __restrict__ al0, const float* __restrict__ ar0,
               const float* __restrict__ al1, const float* __restrict__ ar1,
               float* __restrict__ Cskip, float* __restrict__ Cfc0,
               float* __restrict__ Cfc1,
               float* __restrict__ el0, float* __restrict__ er0,
               float* __restrict__ el1, float* __restrict__ er1,
               int aff_slot, const float* __restrict__ ng,
               const float* __restrict__ nb) {
    __shared__ float As[2][16][128];
    __shared__ float Ws[2][16][128];
    __shared__ float s_sc[NF], s_sh[NF];
    if (blockIdx.y == 0) {
        gemm_body(A, Wskip, bskip, Cskip, nullptr, nullptr, nullptr, nullptr, As, Ws,
                  s_sc, s_sh, aff_slot, ng, nb, false, 0);
    } else if (blockIdx.y == 1) {
        gemm_body(A, Wfc0, nullptr, Cfc0, al0, ar0, el0, er0, As, Ws,
                  s_sc, s_sh, aff_slot, ng, nb, false, 0);
    } else {
        gemm_body(A, Wfc1, nullptr, Cfc1, al1, ar1, el1, er1, As, Ws,
                  s_sc, s_sh, aff_slot, ng, nb, false, 0);
    }
}

// ---------------- fused dual-relation GAT agg + finalize + BN stats --------
__device__ __forceinline__ float agg_one_rel(
    int r, int d, int h, int co,
    const float* __restrict__ el, const float* __restrict__ er,
    const float* __restrict__ fs, float4* acc_out) {
    const int beg = g_rowptr[r][d];
    const int end = g_rowptr[r][d + 1];
    const float er_h = er[d * NH + h];
    float4 acc = make_float4(0.f, 0.f, 0.f, 0.f);
    float sh = 0.f;
    const int n4 = (end - beg) >> 2;
    int s0 = 0, s1 = 0, s2 = 0, s3 = 0;
    if (n4 > 0) {
        s0 = g_colsrc[r][beg];     s1 = g_colsrc[r][beg + 1];
        s2 = g_colsrc[r][beg + 2]; s3 = g_colsrc[r][beg + 3];
    }
    for (int it = 0; it < n4; it++) {
        int t0 = s0, t1 = s1, t2 = s2, t3 = s3;
        int nb2 = beg + (it + 1) * 4;
        if (it + 1 < n4) {                    // prefetch next quad of indices
            s0 = g_colsrc[r][nb2];     s1 = g_colsrc[r][nb2 + 1];
            s2 = g_colsrc[r][nb2 + 2]; s3 = g_colsrc[r][nb2 + 3];
        }
        float el0 = el[t0 * NH + h];
        float el1 = el[t1 * NH + h];
        float el2 = el[t2 * NH + h];
        float el3 = el[t3 * NH + h];
        float4 f0 = *(const float4*)&fs[(size_t)t0 * NF + co];
        float4 f1 = *(const float4*)&fs[(size_t)t1 * NF + co];
        float4 f2 = *(const float4*)&fs[(size_t)t2 * NF + co];
        float4 f3 = *(const float4*)&fs[(size_t)t3 * NF + co];
        float v0 = el0 + er_h; v0 = v0 > 0.f ? v0 : NEG_SLOPE * v0;
        float v1 = el1 + er_h; v1 = v1 > 0.f ? v1 : NEG_SLOPE * v1;
        float v2 = el2 + er_h; v2 = v2 > 0.f ? v2 : NEG_SLOPE * v2;
        float v3 = el3 + er_h; v3 = v3 > 0.f ? v3 : NEG_SLOPE * v3;
        float w0 = expf(v0), w1 = expf(v1), w2 = expf(v2), w3 = expf(v3);
        sh += (w0 + w1) + (w2 + w3);
        acc.x = fmaf(w0, f0.x, acc.x); acc.y = fmaf(w0, f0.y, acc.y);
        acc.z = fmaf(w0, f0.z, acc.z); acc.w = fmaf(w0, f0.w, acc.w);
        acc.x = fmaf(w1, f1.x, acc.x); acc.y = fmaf(w1, f1.y, acc.y);
        acc.z = fmaf(w1, f1.z, acc.z); acc.w = fmaf(w1, f1.w, acc.w);
        acc.x = fmaf(w2, f2.x, acc.x); acc.y = fmaf(w2, f2.y, acc.y);
        acc.z = fmaf(w2, f2.z, acc.z); acc.w = fmaf(w2, f2.w, acc.w);
        acc.x = fmaf(w3, f3.x, acc.x); acc.y = fmaf(w3, f3.y, acc.y);
        acc.z = fmaf(w3, f3.z, acc.z); acc.w = fmaf(w3, f3.w, acc.w);
    }
    for (int e = beg + n4 * 4; e < end; e++) {
        int s = g_colsrc[r][e];
        float elA = el[s * NH + h];
        float4 fa = *(const float4*)&fs[(size_t)s * NF + co];
        float vA = elA + er_h; vA = vA > 0.f ? vA : NEG_SLOPE * vA;
        float wA = expf(vA);
        sh += wA;
        acc.x = fmaf(wA, fa.x, acc.x); acc.y = fmaf(wA, fa.y, acc.y);
        acc.z = fmaf(wA, fa.z, acc.z); acc.w = fmaf(wA, fa.w, acc.w);
    }
    *acc_out = acc;
    return (end > beg) ? (1.f / sh) : 0.f;
}

__global__ __launch_bounds__(256)
void gat_agg2(const float* __restrict__ ela, const float* __restrict__ era,
              const float* __restrict__ fsa,
              const float* __restrict__ elb, const float* __restrict__ erb,
              const float* __restrict__ fsb,
              const float* __restrict__ h1,
              const float* __restrict__ cb0, const float* __restrict__ cb1,
              float* __restrict__ t_out, int slot) {
    __shared__ float ts[8][NF];
    const int wid = threadIdx.x >> 5;
    const int lane = threadIdx.x & 31;
    const int d = blockIdx.x * 8 + wid;        // grid = 6250 -> 50000 warps
    const int h = lane >> 3;
    const int co = lane * 4;

    float4 a0, a1;
    float i0 = agg_one_rel(0, d, h, co, ela, era, fsa, &a0);
    float i1 = agg_one_rel(1, d, h, co, elb, erb, fsb, &a1);

    float4 b0 = *(const float4*)&cb0[co];
    float4 b1 = *(const float4*)&cb1[co];
    float4 hv = *(const float4*)&h1[(size_t)d * NF + co];

    float4 v;
    v.x = fmaf(a0.x, i0, a1.x * i1) + b0.x + b1.x;
    v.y = fmaf(a0.y, i0, a1.y * i1) + b0.y + b1.y;
    v.z = fmaf(a0.z, i0, a1.z * i1) + b0.z + b1.z;
    v.w = fmaf(a0.w, i0, a1.w * i1) + b0.w + b1.w;
    v.x = (v.x > 0.f ? v.x : 0.f) + hv.x;
    v.y = (v.y > 0.f ? v.y : 0.f) + hv.y;
    v.z = (v.z > 0.f ? v.z : 0.f) + hv.z;
    v.w = (v.w > 0.f ? v.w : 0.f) + hv.w;
    *(float4*)&t_out[(size_t)d * NF + co] = v;

    // block-level BN stats (8 nodes x 128 cols)
    *(float4*)&ts[wid][co] = v;
    __syncthreads();
    if (threadIdx.x < NF) {
        int c = threadIdx.x;
        double s_a = 0.0, s_b = 0.0, q_a = 0.0, q_b = 0.0;
#pragma unroll
        for (int w = 0; w < 8; w += 2) {
            float xa = ts[w][c], xb = ts[w + 1][c];
            s_a += xa;                 s_b += xb;
            q_a += (double)xa * xa;    q_b += (double)xb * xb;
        }
        atomicAdd(&g_sum[slot][c], s_a + s_b);
        atomicAdd(&g_sq[slot][c],  q_a + q_b);
    }
}

// ---------------- final 128 -> 16 GEMM, BN affine+relu fused in load -------
// 256 threads, 16 rows per block
__global__ __launch_bounds__(256)
void gemm_out(const float* __restrict__ x, const float* __restrict__ clf_g,
              const float* __restrict__ clf_b, const float* __restrict__ W2,
              const float* __restrict__ b2, float* __restrict__ out, int slot) {
    __shared__ float xs[16][NF];
    int tid = threadIdx.x;
    int col = tid & 127;
    int half = tid >> 7;                 // 0 or 1 -> rows 0..7 / 8..15
    int r0 = blockIdx.x * 16;
    double mu = g_sum[slot][col] / (double)N_NODES;
    double var = g_sq[slot][col] / (double)N_NODES - mu * mu;
    float sc = clf_g[col] * rsqrtf((float)var + BN_EPS);
    float sh = clf_b[col] - (float)mu * sc;
#pragma unroll
    for (int i = 0; i < 8; i++) {
        int row = r0 + half * 8 + i;
        float v = (row < N_NODES) ? fmaf(x[(size_t)row * NF + col], sc, sh) : 0.f;
        xs[half * 8 + i][col] = v > 0.f ? v : 0.f;
    }
    __syncthreads();
    int row = tid >> 4;                  // 0..15
    int c = tid & 15;
    float acc = b2[c];
#pragma unroll 8
    for (int k = 0; k < NF; k++) acc = fmaf(xs[row][k], W2[k * 16 + c], acc);
    if (r0 + row < N_NODES) out[(size_t)(r0 + row) * 16 + c] = acc;
}

// ---------------- host ----------------
extern "C" void kernel_launch(void* const* d_in, const int* in_sizes, int n_in,
                              void* d_out, int out_size) {
    const float* feat     = (const float*)d_in[0];
    const float* fc_W     = (const float*)d_in[1];
    const float* attn_l   = (const float*)d_in[2];
    const float* attn_r   = (const float*)d_in[3];
    const float* conv_b   = (const float*)d_in[4];
    const float* skip_W   = (const float*)d_in[5];
    const float* skip_b   = (const float*)d_in[6];
    const float* norm_g   = (const float*)d_in[7];
    const float* norm_b   = (const float*)d_in[8];
    const float* clf_W1   = (const float*)d_in[9];
    const float* clf_b1   = (const float*)d_in[10];
    const float* clf_g    = (const float*)d_in[11];
    const float* clf_b    = (const float*)d_in[12];
    const float* clf_W2   = (const float*)d_in[13];
    const float* clf_b2   = (const float*)d_in[14];
    const int*   src      = (const int*)d_in[15];
    const int*   dst      = (const int*)d_in[16];
    float* out = (float*)d_out;

    float *h1, *fsa, *fsb, *h2, *ela, *era, *elb, *erb;
    cudaGetSymbolAddress((void**)&h1,  g_h1);
    cudaGetSymbolAddress((void**)&fsa, g_fsa);
    cudaGetSymbolAddress((void**)&fsb, g_fsb);
    cudaGetSymbolAddress((void**)&h2,  g_h2);
    cudaGetSymbolAddress((void**)&ela, g_ela);
    cudaGetSymbolAddress((void**)&era, g_era);
    cudaGetSymbolAddress((void**)&elb, g_elb);
    cudaGetSymbolAddress((void**)&erb, g_erb);

    const int gemm_grid  = (N_NODES + 127) / 128;        // 391
    const int node2_grid = (2 * N_NODES + 255) / 256;
    const int edge2_grid = (2 * N_EDGES + 255) / 256;
    const int agg_grid   = N_NODES / 8;                  // 6250

    // lazily-created side stream + events for the CSR fork (host resources only)
    static cudaStream_t s_csr = nullptr;
    static cudaEvent_t ev_fork = nullptr, ev_join = nullptr;
    if (s_csr == nullptr) {
        cudaStreamCreate(&s_csr);
        cudaEventCreateWithFlags(&ev_fork, cudaEventDisableTiming);
        cudaEventCreateWithFlags(&ev_join, cudaEventDisableTiming);
    }

    // ---- fork: CSR build + stats zero on side stream ----
    cudaEventRecord(ev_fork, 0);
    cudaStreamWaitEvent(s_csr, ev_fork, 0);
    zero_deg_all<<<node2_grid, 256, 0, s_csr>>>();
    hist_deg_all<<<edge2_grid, 256, 0, s_csr>>>(dst);
    scan_blocks_all<<<2 * N_SCANB, SCAN_B, 0, s_csr>>>();
    scan_bsum_all<<<2, 64, 0, s_csr>>>();
    scan_finish_all<<<node2_grid, 256, 0, s_csr>>>();
    scatter_csr_all<<<edge2_grid, 256, 0, s_csr>>>(src, dst);
    cudaEventRecord(ev_join, s_csr);

    dim3 g3(gemm_grid, 3);
    // ---- layer 1 GEMMs (raw feat), concurrent with the CSR build ----
    gemm128x3<<<g3, 256>>>(feat,
                           skip_W, skip_b,
                           fc_W, fc_W + (size_t)NF * NF,
                           attn_l, attn_r,
                           attn_l + NF, attn_r + NF,
                           h1, fsa, fsb, ela, era, elb, erb,
                           -1, nullptr, nullptr);
    cudaStreamWaitEvent(0, ev_join, 0);   // join before first CSR consumer

    // layer 1 agg -> t1 in h2, BN stats slot 0
    gat_agg2<<<agg_grid, 256>>>(ela, era, fsa, elb, erb, fsb,
                                h1, conv_b, conv_b + NF, h2, 0);

    // ---- layer 2 GEMMs: read t1 with fused BN affine (slot 0) ----
    gemm128x3<<<g3, 256>>>(h2,
                           skip_W + NF * NF, skip_b + NF,
                           fc_W + (size_t)2 * NF * NF,
                           fc_W + (size_t)3 * NF * NF,
                           attn_l + 2 * NF, attn_r + 2 * NF,
                           attn_l + 3 * NF, attn_r + 3 * NF,
                           h1, fsa, fsb, ela, era, elb, erb,
                           0, norm_g, norm_b);

    // layer 2 agg -> t2 in h2 (t1 consumed), BN stats slot 1
    gat_agg2<<<agg_grid, 256>>>(ela, era, fsa, elb, erb, fsb,
                                h1, conv_b + 2 * NF, conv_b + 3 * NF, h2, 1);

    // classifier: read t2 with fused BN affine (slot 1), emit stats slot 2
    gemm128_stats<<<gemm_grid, 256>>>(h2, clf_W1, clf_b1, h1,
                                      1, norm_g + NF, norm_b + NF, 2);
    gemm_out<<<(N_NODES + 15) / 16, 256>>>(h1, clf_g, clf_b, clf_W2, clf_b2, out, 2);
}